// round 11
// baseline (speedup 1.0000x reference)
#include <cuda_runtime.h>
#include <cuda_bf16.h>
#include <cstdint>

#define BB   64
#define CIN  12
#define LL   4096
#define TT   20
#define NC1  64
#define NC2  64
#define NCLS 4
#define NLT  128
#define NTILES 32
#define NBP  132

typedef unsigned long long ull;
typedef unsigned int u32;

__device__ float g_pool[BB * NC2];
// bf16 A fragments (K=64 per-tap, hi/lo planes), exact mma lane order
__device__ u32 g_Ah[6144];
__device__ u32 g_Al[6144];

// mma.sync m16n8k16 bf16, fp32 accumulate (baseline PTX, sm_80+)
#define MMA16816(d, a, b) \
    asm volatile("mma.sync.aligned.m16n8k16.row.col.f32.bf16.bf16.f32 " \
        "{%0,%1,%2,%3}, {%4,%5,%6,%7}, {%8,%9}, {%0,%1,%2,%3};" \
        : "+f"((d)[0]), "+f"((d)[1]), "+f"((d)[2]), "+f"((d)[3]) \
        : "r"((a).x), "r"((a).y), "r"((a).z), "r"((a).w), \
          "r"((b).x), "r"((b).y))

// channel permutation matching the multiply-spread decode:
// bits (i, i+16) of half-word mask -> k-positions (2a, 2a+1), a = h*16+i
__device__ __forceinline__ int chan_for_k(int kappa) {
    int a  = kappa >> 1;
    int hh = a >> 4;
    int ii = a & 15;
    return hh * 32 + ii + ((kappa & 1) << 4);
}

// ---------------------------------------------------------------------------
// k_pre: zero pool + build per-tap bf16 A fragments (hi/lo split, exact)
// ---------------------------------------------------------------------------
__global__ void k_pre(const float* __restrict__ w2) {
    int i = blockIdx.x * blockDim.x + threadIdx.x;
    if (i < BB * NC2) g_pool[i] = 0.0f;
    if (i < 6144) {
        int r    = i & 3;
        int idx4 = i >> 2;
        int lane = idx4 & 31;
        int rest = idx4 >> 5;        // (j*3+kk)*4 + s
        int s    = rest & 3;
        int kkj  = rest >> 2;
        int kk   = kkj % 3;
        int j    = kkj / 3;
        int gid  = lane >> 2;
        int t4   = lane & 3;
        int m    = 16 * j + gid + 8 * (r & 1);
        u32 hi = 0, lo = 0;
#pragma unroll
        for (int e = 0; e < 2; e++) {
            int kappa = 16 * s + 2 * t4 + 8 * (r >> 1) + e;
            int c1    = chan_for_k(kappa);
            float wv  = w2[m * (NC1 * 3) + c1 * 3 + kk];
            __nv_bfloat16 bh = __float2bfloat16(wv);
            __nv_bfloat16 bl = __float2bfloat16(wv - __bfloat162float(bh));
            hi |= (u32)__bfloat16_as_ushort(bh) << (16 * e);
            lo |= (u32)__bfloat16_as_ushort(bl) << (16 * e);
        }
        g_Ah[i] = hi;
        g_Al[i] = lo;
    }
}

// ---------------------------------------------------------------------------
// k_all: fully fused conv1 (FMA pipe) + conv2 HMMA (tensor pipe) + LIF + pool.
// CTA = (b, 128-l tile), 512 threads = 16 warps.
// Per t-pair: decode smem spike bits -> bf16 B frags (both t), barrier,
// then 24 MMA groups with ONE conv1 task for pair tp+1 interleaved after each
// group (fills idle issue slots while the tensor unit is saturated),
// then stage x for pair tp+2, barrier.
// smem u32: Ash[0,6144) Asl[6144,12288) B[12288,20736) xs[20736,27072)
//           bits[27072,28112)  => 112448 bytes
// ---------------------------------------------------------------------------
#define OFF_ASL  6144
#define OFF_B    12288
#define OFF_XS   20736
#define OFF_BITS 27072
#define XSBUF    3168          // u32 per xs buffer (12*132 float2)
#define ALL_SMEM (28112 * 4)

__device__ __forceinline__ void conv1_task(
        const float2* __restrict__ xsb, u32* __restrict__ bitsb, int lx,
        const float* wr, float bias, float gain, float th1,
        int h, int lane, int l0) {
    int gl = l0 - 1 + lx;
    float a0 = 0.0f, a1 = 0.0f;
    if (gl >= 0 && gl < LL) {
#pragma unroll
        for (int c = 0; c < CIN; c++)
#pragma unroll
            for (int k = 0; k < 3; k++) {
                float2 xv = xsb[c * 132 + lx + k];
                float  wv = wr[c * 3 + k];
                a0 = fmaf(xv.x, wv, a0);
                a1 = fmaf(xv.y, wv, a1);
            }
    }
    u32 m0 = __ballot_sync(0xffffffffu, (a0 + bias) * gain >= th1);
    u32 m1 = __ballot_sync(0xffffffffu, (a1 + bias) * gain >= th1);
    if (gl < 0 || gl >= LL) { m0 = 0; m1 = 0; }
    if (lane == 0) {
        bitsb[h * 130 + lx]       = m0;
        bitsb[(2 + h) * 130 + lx] = m1;
    }
}

__global__ __launch_bounds__(512, 1) void k_all(
        const float* __restrict__ x,
        const float* __restrict__ w1,
        const float* __restrict__ b1,
        const float* __restrict__ b2,
        const float* __restrict__ pgain,
        const float* __restrict__ pth1,
        const float* __restrict__ pth2) {
    extern __shared__ __align__(16) u32 smw[];
    u32*    Ash  = smw;
    u32*    Asl  = smw + OFF_ASL;
    u32*    Bs   = smw + OFF_B;
    float2* xs   = (float2*)(smw + OFF_XS);
    u32*    bits = smw + OFF_BITS;

    const int tid  = threadIdx.x;
    const int b    = blockIdx.x >> 5;
    const int l0   = (blockIdx.x & 31) * NLT;
    const int w    = tid >> 5;
    const int lane = tid & 31;

    // stage A fragments (L2-hot, identical for every CTA)
    for (int i = tid; i < 1536; i += 512) {
        ((uint4*)Ash)[i] = ((const uint4*)g_Ah)[i];
        ((uint4*)Asl)[i] = ((const uint4*)g_Al)[i];
    }

    // ---- conv1 per-warp state: half (w&1), lane = channel in half ----
    const int   h    = w & 1;
    const int   lrow = w >> 1;          // lx = lrow + 8k
    const int   c1   = h * 32 + lane;
    const float gain = *pgain;
    const float th1  = *pth1;
    const float c1b  = b1[c1];
    float wr[CIN * 3];
#pragma unroll
    for (int i = 0; i < CIN * 3; i++)
        wr[i] = w1[c1 * (CIN * 3) + i];

    // ---- MMA per-warp state ----
    const int j    = w & 3;
    const int q    = w >> 2;
    const int gid  = lane >> 2;
    const int tid4 = lane & 3;
    const float th2    = *pth2;
    const float invtau = 1.0f / 0.9f;
    const float bia0   = b2[16 * j + gid];
    const float bia1   = b2[16 * j + gid + 8];

    // decode task assignment (260 tasks over 512 threads)
    const bool dact = tid < 260;
    const int  dh   = (tid >= 130) ? 1 : 0;
    const int  dn   = tid - 130 * dh;

    float v2[16], cnt[16];
#pragma unroll
    for (int i = 0; i < 16; i++) { v2[i] = 0.0f; cnt[i] = 0.0f; }

    // ---- x staging helper (inline) ----
#define STAGE_X(buf, pp)                                                      \
    do {                                                                      \
        float2* xd = xs + (buf) * (XSBUF / 2);                                \
        for (int i = tid; i < CIN * 132; i += 512) {                          \
            int c = i / 132, lxs = i % 132;                                   \
            int gl = l0 - 2 + lxs;                                            \
            float2 v = make_float2(0.0f, 0.0f);                               \
            if (gl >= 0 && gl < LL)                                           \
                v = *(const float2*)&x[(((size_t)(b * CIN + c)) * LL + gl) *  \
                                       TT + 2 * (pp)];                        \
            xd[i] = v;                                                        \
        }                                                                     \
    } while (0)

    // ================= prologue: pair 0 bits + xs for pairs 0,1 ============
    STAGE_X(0, 0);
    __syncthreads();
    {
        const float2* xsb = xs;            // buffer 0
        u32* bitsb = bits;                 // buffer 0
#pragma unroll 1
        for (int k = 0; k < 17; k++) {
            int lx = lrow + 8 * k;
            if (lx < 130)
                conv1_task(xsb, bitsb, lx, wr, c1b, gain, th1, h, lane, l0);
        }
    }
    STAGE_X(1, 1);
    __syncthreads();

    // ============================ main loop =================================
#pragma unroll 1
    for (int tp = 0; tp < TT / 2; tp++) {
        // ---- decode pair tp from smem bits -> bf16 B frags for t0, t1 ----
        if (dact) {
            const u32* bb = bits + (tp & 1) * 520;
            u32 mc0 = bb[dh * 130 + dn];
            u32 mc1 = bb[(2 + dh) * 130 + dn];
            u32 o[16];
#pragma unroll
            for (int i = 0; i < 16; i++)
                o[i] = ((mc0 >> i) & 0x00010001u) * 0x3F80u;
            u32* r0 = Bs + ((2 * dh)     * NBP + dn) * 8;
            u32* r1 = Bs + ((2 * dh + 1) * NBP + dn) * 8;
            ((uint4*)r0)[0] = make_uint4(o[0],  o[4],  o[1],  o[5]);
            ((uint4*)r0)[1] = make_uint4(o[2],  o[6],  o[3],  o[7]);
            ((uint4*)r1)[0] = make_uint4(o[8],  o[12], o[9],  o[13]);
            ((uint4*)r1)[1] = make_uint4(o[10], o[14], o[11], o[15]);
#pragma unroll
            for (int i = 0; i < 16; i++)
                o[i] = ((mc1 >> i) & 0x00010001u) * 0x3F80u;
            r0 = Bs + 4224 + ((2 * dh)     * NBP + dn) * 8;
            r1 = Bs + 4224 + ((2 * dh + 1) * NBP + dn) * 8;
            ((uint4*)r0)[0] = make_uint4(o[0],  o[4],  o[1],  o[5]);
            ((uint4*)r0)[1] = make_uint4(o[2],  o[6],  o[3],  o[7]);
            ((uint4*)r1)[0] = make_uint4(o[8],  o[12], o[9],  o[13]);
            ((uint4*)r1)[1] = make_uint4(o[10], o[14], o[11], o[15]);
        }
        __syncthreads();

        const int     pp    = tp + 1;                         // pair produced
        const float2* xsb   = xs + (pp & 1) * (XSBUF / 2);
        u32*          bitsb = bits + (pp & 1) * 520;
        const bool    doc1  = (tp < TT / 2 - 1);

        // ---- MMA (t0, t1) with conv1 tasks interleaved per group ----
#pragma unroll 1
        for (int tt = 0; tt < 2; tt++) {
            u32* Bq = Bs + tt * 4224;
            float acc[4][4];
#pragma unroll
            for (int nt = 0; nt < 4; nt++)
#pragma unroll
                for (int r = 0; r < 4; r++) acc[nt][r] = 0.0f;

#pragma unroll
            for (int g = 0; g < 12; g++) {
                const int s  = g / 3;
                const int kk = g % 3;
                int abase = (((j * 3 + kk) * 4 + s) * 32 + lane) * 4;
                uint4 ah = *(const uint4*)&Ash[abase];
                uint4 al = *(const uint4*)&Asl[abase];
#pragma unroll
                for (int nt = 0; nt < 4; nt++) {
                    int boff = (s * NBP + q * 32 + nt * 8 + gid + kk) * 8 +
                               tid4 * 2;
                    uint2 bbf = *(const uint2*)&Bq[boff];
                    MMA16816(acc[nt], ah, bbf);
                    MMA16816(acc[nt], al, bbf);
                }
                // interleaved conv1 task (fills idle issue slots)
                if (doc1) {
                    int k = tt * 12 + g;
                    if (k < 17) {
                        int lx = lrow + 8 * k;
                        if (lx < 130)
                            conv1_task(xsb, bitsb, lx, wr, c1b, gain, th1,
                                       h, lane, l0);
                    }
                }
            }

            // ---- LIF epilogue in registers ----
#pragma unroll
            for (int nt = 0; nt < 4; nt++)
#pragma unroll
                for (int r = 0; r < 4; r++) {
                    float bia = (r >> 1) ? bia1 : bia0;
                    float i2  = (acc[nt][r] + bia) * gain;
                    int idx = nt * 4 + r;
                    v2[idx] += (i2 - v2[idx]) * invtau;
                    if (v2[idx] >= th2) { cnt[idx] += 1.0f; v2[idx] = 0.0f; }
                }
        }

        // ---- stage x for pair tp+2 into the buffer freed this iteration ----
        if (tp < TT / 2 - 2)
            STAGE_X(tp & 1, tp + 2);
        __syncthreads();
    }

    // ---- pool: sum counts per c2 ----
    float t0 = 0.0f, t1 = 0.0f;
#pragma unroll
    for (int nt = 0; nt < 4; nt++)
#pragma unroll
        for (int r = 0; r < 4; r++) {
            if (r >> 1) t1 += cnt[nt * 4 + r];
            else        t0 += cnt[nt * 4 + r];
        }
    t0 += __shfl_xor_sync(0xffffffffu, t0, 1);
    t0 += __shfl_xor_sync(0xffffffffu, t0, 2);
    t1 += __shfl_xor_sync(0xffffffffu, t1, 1);
    t1 += __shfl_xor_sync(0xffffffffu, t1, 2);
    if (tid4 == 0) {
        atomicAdd(&g_pool[b * NC2 + 16 * j + gid],     t0);   // integer-valued
        atomicAdd(&g_pool[b * NC2 + 16 * j + gid + 8], t1);
    }
#undef STAGE_X
}

// ---------------------------------------------------------------------------
// k_fc: pooled = counts / (T*L); logits = pooled @ fc_w.T + fc_b
// ---------------------------------------------------------------------------
__global__ void k_fc(const float* __restrict__ fw,
                     const float* __restrict__ fb,
                     float* __restrict__ out) {
    int tid = threadIdx.x;
    int b = tid >> 2;
    int n = tid & 3;
    const float sc = 1.0f / (float)(TT * LL);
    float s = fb[n];
#pragma unroll
    for (int c = 0; c < NC2; c++)
        s += (g_pool[b * NC2 + c] * sc) * fw[n * NC2 + c];
    out[b * NCLS + n] = s;
}

// ---------------------------------------------------------------------------
extern "C" void kernel_launch(void* const* d_in, const int* in_sizes, int n_in,
                              void* d_out, int out_size) {
    const float* x    = (const float*)d_in[0];
    const float* w1   = (const float*)d_in[1];
    const float* b1   = (const float*)d_in[2];
    const float* w2   = (const float*)d_in[3];
    const float* b2   = (const float*)d_in[4];
    const float* gain = (const float*)d_in[5];
    const float* th1  = (const float*)d_in[6];
    const float* th2  = (const float*)d_in[7];
    const float* fw   = (const float*)d_in[8];
    const float* fb   = (const float*)d_in[9];
    float* out = (float*)d_out;

    cudaFuncSetAttribute(k_all, cudaFuncAttributeMaxDynamicSharedMemorySize,
                         ALL_SMEM);

    k_pre<<<24, 256>>>(w2);

    k_all<<<BB * NTILES, 512, ALL_SMEM>>>(x, w1, b1, b2, gain, th1, th2);

    k_fc<<<1, 256>>>(fw, fb, out);
}

// round 12
// speedup vs baseline: 1.0076x; 1.0076x over previous
#include <cuda_runtime.h>
#include <cuda_bf16.h>
#include <cstdint>

#define BB   64
#define CIN  12
#define LL   4096
#define TT   20
#define NC1  64
#define NC2  64
#define NCLS 4
#define NLT  128                 // l positions per tile
#define NTILES (LL / NLT)        // 32
#define NBP  132                 // padded B rows (130 used)
#define NCHK 4                   // batch chunks for stream overlap
#define BCHK (BB / NCHK)         // 16

typedef unsigned long long ull;
typedef unsigned int u32;

// spike bits: 2x u32 per (b,t,l)
__device__ u32 g_s1[BB * TT * LL * 2];
// per (b,c2) spike counts
__device__ float g_pool[BB * NC2];
// bf16 A fragments (K=64 per-tap, hi/lo planes), exact mma lane order
__device__ u32 g_Ah[6144];
__device__ u32 g_Al[6144];

// ---------------- packed f32x2 helpers (conv1) ------------------------------
#define FMA_F32X2(d, a, b, c) \
    asm("fma.rn.f32x2 %0, %1, %2, %3;" : "=l"(d) : "l"(a), "l"(b), "l"(c))
#define PACK_F32X2(out, lo, hi) \
    asm("mov.b64 %0, {%1, %2};" : "=l"(out) : "f"(lo), "f"(hi))
#define UNPACK_F32X2(lo, hi, in) \
    asm("mov.b64 {%0, %1}, %2;" : "=f"(lo), "=f"(hi) : "l"(in))

// mma.sync m16n8k16 bf16, fp32 accumulate (baseline PTX, sm_80+)
#define MMA16816(d, a, b) \
    asm volatile("mma.sync.aligned.m16n8k16.row.col.f32.bf16.bf16.f32 " \
        "{%0,%1,%2,%3}, {%4,%5,%6,%7}, {%8,%9}, {%0,%1,%2,%3};" \
        : "+f"((d)[0]), "+f"((d)[1]), "+f"((d)[2]), "+f"((d)[3]) \
        : "r"((a).x), "r"((a).y), "r"((a).z), "r"((a).w), \
          "r"((b).x), "r"((b).y))

// channel permutation matching the multiply-spread decode:
// bits (i, i+16) of half-word mask -> k-positions (2a, 2a+1), a = h*16+i
__device__ __forceinline__ int chan_for_k(int kappa) {
    int a  = kappa >> 1;
    int hh = a >> 4;
    int ii = a & 15;
    return hh * 32 + ii + ((kappa & 1) << 4);
}

// ---------------------------------------------------------------------------
// k_pre: zero pool + build per-tap bf16 A fragments (hi/lo split, exact)
// ---------------------------------------------------------------------------
__global__ void k_pre(const float* __restrict__ w2) {
    int i = blockIdx.x * blockDim.x + threadIdx.x;
    if (i < BB * NC2) g_pool[i] = 0.0f;
    if (i < 6144) {
        int r    = i & 3;
        int idx4 = i >> 2;
        int lane = idx4 & 31;
        int rest = idx4 >> 5;        // (j*3+kk)*4 + s
        int s    = rest & 3;
        int kkj  = rest >> 2;
        int kk   = kkj % 3;
        int j    = kkj / 3;
        int gid  = lane >> 2;
        int t4   = lane & 3;
        int m    = 16 * j + gid + 8 * (r & 1);
        u32 hi = 0, lo = 0;
#pragma unroll
        for (int e = 0; e < 2; e++) {
            int kappa = 16 * s + 2 * t4 + 8 * (r >> 1) + e;
            int c1    = chan_for_k(kappa);
            float wv  = w2[m * (NC1 * 3) + c1 * 3 + kk];
            __nv_bfloat16 bh = __float2bfloat16(wv);
            __nv_bfloat16 bl = __float2bfloat16(wv - __bfloat162float(bh));
            hi |= (u32)__bfloat16_as_ushort(bh) << (16 * e);
            lo |= (u32)__bfloat16_as_ushort(bl) << (16 * e);
        }
        g_Ah[i] = hi;
        g_Al[i] = lo;
    }
}

// ---------------------------------------------------------------------------
// k_conv1: conv1 + threshold -> bit-packed spikes (TAU1=1 => stateless).
// Chunked over batch: b = bbase + blockIdx.y.
// ---------------------------------------------------------------------------
__global__ __launch_bounds__(256) void k_conv1(
        const float* __restrict__ x,
        const float* __restrict__ w1,
        const float* __restrict__ b1,
        const float* __restrict__ pgain,
        const float* __restrict__ pth1,
        int bbase) {
    __shared__ __align__(16) float s_x[CIN][34][TT];

    const int l0  = blockIdx.x * 32;
    const int b   = bbase + blockIdx.y;
    const int tid = threadIdx.x;

    for (int i = tid; i < CIN * 34 * TT; i += 256) {
        int c   = i / (34 * TT);
        int rem = i % (34 * TT);
        int lx  = rem / TT;
        int t   = rem % TT;
        int gl  = l0 - 1 + lx;
        float v = 0.0f;
        if (gl >= 0 && gl < LL)
            v = x[((size_t)(b * CIN + c) * LL + gl) * TT + t];
        s_x[c][lx][t] = v;
    }

    const int w    = tid >> 5;
    const int lane = tid & 31;
    const int half = w & 1;
    const int pair = w >> 1;
    const int c1   = half * 32 + lane;

    ull wrp[CIN][3];
#pragma unroll
    for (int c = 0; c < CIN; c++)
#pragma unroll
        for (int k = 0; k < 3; k++) {
            float wv = w1[c1 * (CIN * 3) + c * 3 + k];
            PACK_F32X2(wrp[c][k], wv, wv);
        }
    const float bias = b1[c1];
    const float gain = *pgain;
    const float th1  = *pth1;

    __syncthreads();

    for (int task = pair; task < 160; task += 4) {
        int ll = task & 31;
        int tg = task >> 5;
        int t0 = tg * 4;
        ull a01 = 0ull, a23 = 0ull;
#pragma unroll
        for (int c = 0; c < CIN; c++) {
#pragma unroll
            for (int k = 0; k < 3; k++) {
                ulonglong2 xq = *(const ulonglong2*)&s_x[c][ll + k][t0];
                FMA_F32X2(a01, xq.x, wrp[c][k], a01);
                FMA_F32X2(a23, xq.y, wrp[c][k], a23);
            }
        }
        float a[4];
        UNPACK_F32X2(a[0], a[1], a01);
        UNPACK_F32X2(a[2], a[3], a23);
        int gl = l0 + ll;
#pragma unroll
        for (int j = 0; j < 4; j++) {
            float i1 = (a[j] + bias) * gain;
            unsigned m = __ballot_sync(0xffffffffu, i1 >= th1);
            if (lane == 0)
                g_s1[((size_t)(b * TT + (t0 + j)) * LL + gl) * 2 + half] = m;
        }
    }
}

// ---------------------------------------------------------------------------
// k_snn: conv2 via mma.sync, 2-timestep batched (unchanged from R10).
// Chunked over batch: b = bbase + (blockIdx.x >> 5).
// ---------------------------------------------------------------------------
#define SNN_SMEM ((12288 + 2 * 8448) * 4)     // 116736 bytes

__global__ __launch_bounds__(512, 1) void k_snn(
        const float* __restrict__ b2,
        const float* __restrict__ pgain,
        const float* __restrict__ pth2,
        int bbase) {
    extern __shared__ __align__(16) u32 smw[];
    u32* Ash = smw;
    u32* Asl = smw + 6144;
    u32* Bs  = smw + 12288;

    const int tid = threadIdx.x;
    const int b   = bbase + (blockIdx.x >> 5);
    const int l0  = (blockIdx.x & 31) * NLT;

    // stage A fragments (L2-hot, identical for every CTA)
    for (int i = tid; i < 1536; i += 512) {
        ((uint4*)Ash)[i] = ((const uint4*)g_Ah)[i];
        ((uint4*)Asl)[i] = ((const uint4*)g_Al)[i];
    }

    const int w    = tid >> 5;
    const int lane = tid & 31;
    const int j    = w & 3;       // m-tile (16 c2 rows)
    const int q    = w >> 2;      // n-quarter (32 l)
    const int gid  = lane >> 2;
    const int tid4 = lane & 3;

    const float gain   = *pgain;
    const float th2    = *pth2;
    const float invtau = 1.0f / 0.9f;
    const float bia0   = b2[16 * j + gid];
    const float bia1   = b2[16 * j + gid + 8];

    // decode task assignment (260 tasks over 512 threads)
    const bool dact = tid < 260;
    int dh = 0, dn = 0;
    bool inrange = false;
    size_t gstep = 0, gaddr = 0;
    if (dact) {
        dh = (tid >= 130) ? 1 : 0;
        dn = tid - 130 * dh;
        int gl  = l0 - 1 + dn;
        inrange = (gl >= 0 && gl < LL);
        if (inrange) {
            gaddr = ((size_t)(b * TT) * LL + gl) * 2 + dh;
            gstep = (size_t)LL * 2;
        }
    }

    float v2[16], cnt[16];
#pragma unroll
    for (int i = 0; i < 16; i++) { v2[i] = 0.0f; cnt[i] = 0.0f; }

    u32 m0n = 0, m1n = 0;
    if (dact && inrange) {
        m0n = g_s1[gaddr];
        m1n = g_s1[gaddr + gstep];
    }

    __syncthreads();

#pragma unroll 1
    for (int tp = 0; tp < TT / 2; tp++) {
        const int p = tp & 1;
        u32* Bq0 = Bs + p * 8448;
        u32* Bq1 = Bq0 + 4224;

        // ---- decode both timesteps of the pair; prefetch next pair ----
        u32 mc0 = m0n, mc1 = m1n;
        if (dact && inrange && tp + 1 < TT / 2) {
            m0n = g_s1[gaddr + (size_t)(2 * tp + 2) * gstep];
            m1n = g_s1[gaddr + (size_t)(2 * tp + 3) * gstep];
        }
        if (dact) {
            u32 o[16];
#pragma unroll
            for (int i = 0; i < 16; i++)
                o[i] = ((mc0 >> i) & 0x00010001u) * 0x3F80u;
            u32* r0 = Bq0 + ((2 * dh)     * NBP + dn) * 8;
            u32* r1 = Bq0 + ((2 * dh + 1) * NBP + dn) * 8;
            ((uint4*)r0)[0] = make_uint4(o[0],  o[4],  o[1],  o[5]);
            ((uint4*)r0)[1] = make_uint4(o[2],  o[6],  o[3],  o[7]);
            ((uint4*)r1)[0] = make_uint4(o[8],  o[12], o[9],  o[13]);
            ((uint4*)r1)[1] = make_uint4(o[10], o[14], o[11], o[15]);
#pragma unroll
            for (int i = 0; i < 16; i++)
                o[i] = ((mc1 >> i) & 0x00010001u) * 0x3F80u;
            r0 = Bq1 + ((2 * dh)     * NBP + dn) * 8;
            r1 = Bq1 + ((2 * dh + 1) * NBP + dn) * 8;
            ((uint4*)r0)[0] = make_uint4(o[0],  o[4],  o[1],  o[5]);
            ((uint4*)r0)[1] = make_uint4(o[2],  o[6],  o[3],  o[7]);
            ((uint4*)r1)[0] = make_uint4(o[8],  o[12], o[9],  o[13]);
            ((uint4*)r1)[1] = make_uint4(o[10], o[14], o[11], o[15]);
        }
        __syncthreads();

        // ---- mma: 4 ksteps x 3 taps; each A load feeds both timesteps ----
        float acc0[4][4], acc1[4][4];
#pragma unroll
        for (int nt = 0; nt < 4; nt++)
#pragma unroll
            for (int r = 0; r < 4; r++) { acc0[nt][r] = 0.0f; acc1[nt][r] = 0.0f; }

#pragma unroll
        for (int s = 0; s < 4; s++) {
#pragma unroll
            for (int kk = 0; kk < 3; kk++) {
                int abase = (((j * 3 + kk) * 4 + s) * 32 + lane) * 4;
                uint4 ah = *(const uint4*)&Ash[abase];
                uint4 al = *(const uint4*)&Asl[abase];
#pragma unroll
                for (int nt = 0; nt < 4; nt++) {
                    int boff = (s * NBP + q * 32 + nt * 8 + gid + kk) * 8 + tid4 * 2;
                    uint2 bb0 = *(const uint2*)&Bq0[boff];
                    uint2 bb1 = *(const uint2*)&Bq1[boff];
                    MMA16816(acc0[nt], ah, bb0);
                    MMA16816(acc0[nt], al, bb0);
                    MMA16816(acc1[nt], ah, bb1);
                    MMA16816(acc1[nt], al, bb1);
                }
            }
        }

        // ---- LIF epilogue (t then t+1), all in registers ----
#pragma unroll
        for (int nt = 0; nt < 4; nt++)
#pragma unroll
            for (int r = 0; r < 4; r++) {
                float bia = (r >> 1) ? bia1 : bia0;
                int idx = nt * 4 + r;
                float i2 = (acc0[nt][r] + bia) * gain;
                v2[idx] += (i2 - v2[idx]) * invtau;
                if (v2[idx] >= th2) { cnt[idx] += 1.0f; v2[idx] = 0.0f; }
                i2 = (acc1[nt][r] + bia) * gain;
                v2[idx] += (i2 - v2[idx]) * invtau;
                if (v2[idx] >= th2) { cnt[idx] += 1.0f; v2[idx] = 0.0f; }
            }
    }

    // ---- pool: sum counts per c2 ----
    float t0 = 0.0f, t1 = 0.0f;
#pragma unroll
    for (int nt = 0; nt < 4; nt++)
#pragma unroll
        for (int r = 0; r < 4; r++) {
            if (r >> 1) t1 += cnt[nt * 4 + r];
            else        t0 += cnt[nt * 4 + r];
        }
    t0 += __shfl_xor_sync(0xffffffffu, t0, 1);
    t0 += __shfl_xor_sync(0xffffffffu, t0, 2);
    t1 += __shfl_xor_sync(0xffffffffu, t1, 1);
    t1 += __shfl_xor_sync(0xffffffffu, t1, 2);
    if (tid4 == 0) {
        atomicAdd(&g_pool[b * NC2 + 16 * j + gid],     t0);   // integer-valued
        atomicAdd(&g_pool[b * NC2 + 16 * j + gid + 8], t1);
    }
}

// ---------------------------------------------------------------------------
// k_fc: pooled = counts / (T*L); logits = pooled @ fc_w.T + fc_b
// ---------------------------------------------------------------------------
__global__ void k_fc(const float* __restrict__ fw,
                     const float* __restrict__ fb,
                     float* __restrict__ out) {
    int tid = threadIdx.x;
    int b = tid >> 2;
    int n = tid & 3;
    const float sc = 1.0f / (float)(TT * LL);
    float s = fb[n];
#pragma unroll
    for (int c = 0; c < NC2; c++)
        s += (g_pool[b * NC2 + c] * sc) * fw[n * NC2 + c];
    out[b * NCLS + n] = s;
}

// ---------------------------------------------------------------------------
// Launch topology: fork a side stream for conv1 chunks; each k_snn chunk
// waits only on its own conv1 chunk -> conv1 (FMA/LDS pipes) overlaps with
// k_snn (tensor pipe) on co-resident SMs. Standard capture fork/join via
// events; stream/event objects are created lazily on the first
// (non-captured) call, so the captured graph contains only launches.
// ---------------------------------------------------------------------------
extern "C" void kernel_launch(void* const* d_in, const int* in_sizes, int n_in,
                              void* d_out, int out_size) {
    const float* x    = (const float*)d_in[0];
    const float* w1   = (const float*)d_in[1];
    const float* b1   = (const float*)d_in[2];
    const float* w2   = (const float*)d_in[3];
    const float* b2   = (const float*)d_in[4];
    const float* gain = (const float*)d_in[5];
    const float* th1  = (const float*)d_in[6];
    const float* th2  = (const float*)d_in[7];
    const float* fw   = (const float*)d_in[8];
    const float* fb   = (const float*)d_in[9];
    float* out = (float*)d_out;

    static cudaStream_t s2 = nullptr;
    static cudaEvent_t  evFork = nullptr;
    static cudaEvent_t  evC[NCHK];
    if (s2 == nullptr) {
        cudaStreamCreateWithFlags(&s2, cudaStreamNonBlocking);
        cudaEventCreateWithFlags(&evFork, cudaEventDisableTiming);
        for (int c = 0; c < NCHK; c++)
            cudaEventCreateWithFlags(&evC[c], cudaEventDisableTiming);
        cudaFuncSetAttribute(k_snn, cudaFuncAttributeMaxDynamicSharedMemorySize,
                             SNN_SMEM);
    }

    k_pre<<<24, 256>>>(w2);

    // fork side stream off the (possibly capturing) default stream
    cudaEventRecord(evFork, 0);
    cudaStreamWaitEvent(s2, evFork, 0);

    // conv1 chunks on side stream, each followed by its ready-event
    dim3 g1(LL / 32, BCHK);
    for (int c = 0; c < NCHK; c++) {
        k_conv1<<<g1, 256, 0, s2>>>(x, w1, b1, gain, th1, c * BCHK);
        cudaEventRecord(evC[c], s2);
    }

    // k_snn chunks on default stream, each gated on its conv1 chunk.
    // Waiting on evC[c] also chains the join: the final wait (c = NCHK-1)
    // brings s2's entire captured tail back into the origin stream.
    for (int c = 0; c < NCHK; c++) {
        cudaStreamWaitEvent(0, evC[c], 0);
        k_snn<<<BCHK * NTILES, 512, SNN_SMEM>>>(b2, gain, th2, c * BCHK);
    }

    k_fc<<<1, 256>>>(fw, fb, out);
}

// round 13
// speedup vs baseline: 1.1535x; 1.1448x over previous
#include <cuda_runtime.h>
#include <cuda_bf16.h>
#include <cstdint>

#define BB   64
#define CIN  12
#define LL   4096
#define TT   20
#define NC1  64
#define NC2  64
#define NCLS 4
#define NLT  128                 // l positions per tile
#define NTILES (LL / NLT)        // 32
#define NBP  132                 // padded B rows (130 used)

typedef unsigned long long ull;
typedef unsigned int u32;

// spike bits: 2x u32 per (b,t,l)
__device__ u32 g_s1[BB * TT * LL * 2];
// per (b,c2) spike counts
__device__ float g_pool[BB * NC2];
// bf16 A fragments (K=64 per-tap, hi/lo planes), exact mma lane order
__device__ u32 g_Ah[6144];
__device__ u32 g_Al[6144];

// ---------------- packed f32x2 helpers (conv1) ------------------------------
#define FMA_F32X2(d, a, b, c) \
    asm("fma.rn.f32x2 %0, %1, %2, %3;" : "=l"(d) : "l"(a), "l"(b), "l"(c))
#define PACK_F32X2(out, lo, hi) \
    asm("mov.b64 %0, {%1, %2};" : "=l"(out) : "f"(lo), "f"(hi))
#define UNPACK_F32X2(lo, hi, in) \
    asm("mov.b64 {%0, %1}, %2;" : "=f"(lo), "=f"(hi) : "l"(in))

// mma.sync m16n8k16 bf16, fp32 accumulate (baseline PTX, sm_80+)
#define MMA16816(d, a, b) \
    asm volatile("mma.sync.aligned.m16n8k16.row.col.f32.bf16.bf16.f32 " \
        "{%0,%1,%2,%3}, {%4,%5,%6,%7}, {%8,%9}, {%0,%1,%2,%3};" \
        : "+f"((d)[0]), "+f"((d)[1]), "+f"((d)[2]), "+f"((d)[3]) \
        : "r"((a).x), "r"((a).y), "r"((a).z), "r"((a).w), \
          "r"((b).x), "r"((b).y))

// channel permutation matching the multiply-spread decode:
// bits (i, i+16) of half-word mask -> k-positions (2a, 2a+1), a = h*16+i
__device__ __forceinline__ int chan_for_k(int kappa) {
    int a  = kappa >> 1;
    int hh = a >> 4;
    int ii = a & 15;
    return hh * 32 + ii + ((kappa & 1) << 4);
}

// ---------------------------------------------------------------------------
// k_pre: zero pool + build per-tap bf16 A fragments (hi/lo split, exact)
// ---------------------------------------------------------------------------
__global__ void k_pre(const float* __restrict__ w2) {
    int i = blockIdx.x * blockDim.x + threadIdx.x;
    if (i < BB * NC2) g_pool[i] = 0.0f;
    if (i < 6144) {
        int r    = i & 3;
        int idx4 = i >> 2;
        int lane = idx4 & 31;
        int rest = idx4 >> 5;        // (j*3+kk)*4 + s
        int s    = rest & 3;
        int kkj  = rest >> 2;
        int kk   = kkj % 3;
        int j    = kkj / 3;
        int gid  = lane >> 2;
        int t4   = lane & 3;
        int m    = 16 * j + gid + 8 * (r & 1);
        u32 hi = 0, lo = 0;
#pragma unroll
        for (int e = 0; e < 2; e++) {
            int kappa = 16 * s + 2 * t4 + 8 * (r >> 1) + e;
            int c1    = chan_for_k(kappa);
            float wv  = w2[m * (NC1 * 3) + c1 * 3 + kk];
            __nv_bfloat16 bh = __float2bfloat16(wv);
            __nv_bfloat16 bl = __float2bfloat16(wv - __bfloat162float(bh));
            hi |= (u32)__bfloat16_as_ushort(bh) << (16 * e);
            lo |= (u32)__bfloat16_as_ushort(bl) << (16 * e);
        }
        g_Ah[i] = hi;
        g_Al[i] = lo;
    }
}

// ---------------------------------------------------------------------------
// k_conv1: conv1 + threshold -> bit-packed spikes (TAU1=1 => stateless).
// Sliding-window register reuse over l: each warp-pair task = (t-group of 4,
// l-chunk of 4); 6 row loads per channel serve 12 (l,k) tap uses ->
// LDS:FFMA2 ratio 1:4 (was 1:2). Accumulation order (c outer, k inner)
// identical to previous rounds -> bit-identical spikes.
// ---------------------------------------------------------------------------
__global__ __launch_bounds__(256) void k_conv1(
        const float* __restrict__ x,
        const float* __restrict__ w1,
        const float* __restrict__ b1,
        const float* __restrict__ pgain,
        const float* __restrict__ pth1) {
    __shared__ __align__(16) float s_x[CIN][34][TT];

    const int l0  = blockIdx.x * 32;
    const int b   = blockIdx.y;
    const int tid = threadIdx.x;

    // stage x: (l,t) contiguous per channel -> coalesced
    for (int i = tid; i < CIN * 34 * TT; i += 256) {
        int c   = i / (34 * TT);
        int rem = i % (34 * TT);
        int lx  = rem / TT;
        int t   = rem % TT;
        int gl  = l0 - 1 + lx;
        float v = 0.0f;
        if (gl >= 0 && gl < LL)
            v = x[((size_t)(b * CIN + c) * LL + gl) * TT + t];
        s_x[c][lx][t] = v;
    }

    const int w    = tid >> 5;
    const int lane = tid & 31;
    const int half = w & 1;
    const int pair = w >> 1;
    const int c1   = half * 32 + lane;

    ull wrp[CIN][3];
#pragma unroll
    for (int c = 0; c < CIN; c++)
#pragma unroll
        for (int k = 0; k < 3; k++) {
            float wv = w1[c1 * (CIN * 3) + c * 3 + k];
            PACK_F32X2(wrp[c][k], wv, wv);
        }
    const float bias = b1[c1];
    const float gain = *pgain;
    const float th1  = *pth1;

    __syncthreads();

    // 40 chunks = 5 t-groups x 8 l-chunks, split over 4 warp-pairs
#pragma unroll 1
    for (int chunk = pair; chunk < 40; chunk += 4) {
        const int lc = chunk & 7;       // l base = lc*4
        const int tg = chunk >> 3;      // t base = tg*4
        const int t0 = tg * 4;

        ull acc[4][2];
#pragma unroll
        for (int l = 0; l < 4; l++) { acc[l][0] = 0ull; acc[l][1] = 0ull; }

#pragma unroll
        for (int c = 0; c < CIN; c++) {
            ulonglong2 row[6];
#pragma unroll
            for (int i = 0; i < 6; i++)
                row[i] = *(const ulonglong2*)&s_x[c][lc * 4 + i][t0];
#pragma unroll
            for (int l = 0; l < 4; l++)
#pragma unroll
                for (int k = 0; k < 3; k++) {
                    FMA_F32X2(acc[l][0], row[l + k].x, wrp[c][k], acc[l][0]);
                    FMA_F32X2(acc[l][1], row[l + k].y, wrp[c][k], acc[l][1]);
                }
        }

#pragma unroll
        for (int l = 0; l < 4; l++) {
            float a[4];
            UNPACK_F32X2(a[0], a[1], acc[l][0]);
            UNPACK_F32X2(a[2], a[3], acc[l][1]);
            int gl = l0 + lc * 4 + l;
#pragma unroll
            for (int jj = 0; jj < 4; jj++) {
                float i1 = (a[jj] + bias) * gain;
                u32 m = __ballot_sync(0xffffffffu, i1 >= th1);
                if (lane == 0)
                    g_s1[((size_t)(b * TT + t0 + jj) * LL + gl) * 2 + half] = m;
            }
        }
    }
}

// ---------------------------------------------------------------------------
// k_snn: conv2 via mma.sync, 2-timestep batched (unchanged from R10 best).
// ---------------------------------------------------------------------------
#define SNN_SMEM ((12288 + 2 * 8448) * 4)     // 116736 bytes

__global__ __launch_bounds__(512, 1) void k_snn(
        const float* __restrict__ b2,
        const float* __restrict__ pgain,
        const float* __restrict__ pth2) {
    extern __shared__ __align__(16) u32 smw[];
    u32* Ash = smw;
    u32* Asl = smw + 6144;
    u32* Bs  = smw + 12288;

    const int tid = threadIdx.x;
    const int b   = blockIdx.x >> 5;
    const int l0  = (blockIdx.x & 31) * NLT;

    // stage A fragments (L2-hot, identical for every CTA)
    for (int i = tid; i < 1536; i += 512) {
        ((uint4*)Ash)[i] = ((const uint4*)g_Ah)[i];
        ((uint4*)Asl)[i] = ((const uint4*)g_Al)[i];
    }

    const int w    = tid >> 5;
    const int lane = tid & 31;
    const int j    = w & 3;       // m-tile (16 c2 rows)
    const int q    = w >> 2;      // n-quarter (32 l)
    const int gid  = lane >> 2;
    const int tid4 = lane & 3;

    const float gain   = *pgain;
    const float th2    = *pth2;
    const float invtau = 1.0f / 0.9f;
    const float bia0   = b2[16 * j + gid];
    const float bia1   = b2[16 * j + gid + 8];

    // decode task assignment (260 tasks over 512 threads)
    const bool dact = tid < 260;
    int dh = 0, dn = 0;
    bool inrange = false;
    size_t gstep = 0, gaddr = 0;
    if (dact) {
        dh = (tid >= 130) ? 1 : 0;
        dn = tid - 130 * dh;
        int gl  = l0 - 1 + dn;
        inrange = (gl >= 0 && gl < LL);
        if (inrange) {
            gaddr = ((size_t)(b * TT) * LL + gl) * 2 + dh;
            gstep = (size_t)LL * 2;
        }
    }

    float v2[16], cnt[16];
#pragma unroll
    for (int i = 0; i < 16; i++) { v2[i] = 0.0f; cnt[i] = 0.0f; }

    u32 m0n = 0, m1n = 0;
    if (dact && inrange) {
        m0n = g_s1[gaddr];
        m1n = g_s1[gaddr + gstep];
    }

    __syncthreads();

#pragma unroll 1
    for (int tp = 0; tp < TT / 2; tp++) {
        const int p = tp & 1;
        u32* Bq0 = Bs + p * 8448;
        u32* Bq1 = Bq0 + 4224;

        // ---- decode both timesteps of the pair; prefetch next pair ----
        u32 mc0 = m0n, mc1 = m1n;
        if (dact && inrange && tp + 1 < TT / 2) {
            m0n = g_s1[gaddr + (size_t)(2 * tp + 2) * gstep];
            m1n = g_s1[gaddr + (size_t)(2 * tp + 3) * gstep];
        }
        if (dact) {
            u32 o[16];
#pragma unroll
            for (int i = 0; i < 16; i++)
                o[i] = ((mc0 >> i) & 0x00010001u) * 0x3F80u;
            u32* r0 = Bq0 + ((2 * dh)     * NBP + dn) * 8;
            u32* r1 = Bq0 + ((2 * dh + 1) * NBP + dn) * 8;
            ((uint4*)r0)[0] = make_uint4(o[0],  o[4],  o[1],  o[5]);
            ((uint4*)r0)[1] = make_uint4(o[2],  o[6],  o[3],  o[7]);
            ((uint4*)r1)[0] = make_uint4(o[8],  o[12], o[9],  o[13]);
            ((uint4*)r1)[1] = make_uint4(o[10], o[14], o[11], o[15]);
#pragma unroll
            for (int i = 0; i < 16; i++)
                o[i] = ((mc1 >> i) & 0x00010001u) * 0x3F80u;
            r0 = Bq1 + ((2 * dh)     * NBP + dn) * 8;
            r1 = Bq1 + ((2 * dh + 1) * NBP + dn) * 8;
            ((uint4*)r0)[0] = make_uint4(o[0],  o[4],  o[1],  o[5]);
            ((uint4*)r0)[1] = make_uint4(o[2],  o[6],  o[3],  o[7]);
            ((uint4*)r1)[0] = make_uint4(o[8],  o[12], o[9],  o[13]);
            ((uint4*)r1)[1] = make_uint4(o[10], o[14], o[11], o[15]);
        }
        __syncthreads();

        // ---- mma: 4 ksteps x 3 taps; each A load feeds both timesteps ----
        float acc0[4][4], acc1[4][4];
#pragma unroll
        for (int nt = 0; nt < 4; nt++)
#pragma unroll
            for (int r = 0; r < 4; r++) { acc0[nt][r] = 0.0f; acc1[nt][r] = 0.0f; }

#pragma unroll
        for (int s = 0; s < 4; s++) {
#pragma unroll
            for (int kk = 0; kk < 3; kk++) {
                int abase = (((j * 3 + kk) * 4 + s) * 32 + lane) * 4;
                uint4 ah = *(const uint4*)&Ash[abase];
                uint4 al = *(const uint4*)&Asl[abase];
#pragma unroll
                for (int nt = 0; nt < 4; nt++) {
                    int boff = (s * NBP + q * 32 + nt * 8 + gid + kk) * 8 + tid4 * 2;
                    uint2 bb0 = *(const uint2*)&Bq0[boff];
                    uint2 bb1 = *(const uint2*)&Bq1[boff];
                    MMA16816(acc0[nt], ah, bb0);
                    MMA16816(acc0[nt], al, bb0);
                    MMA16816(acc1[nt], ah, bb1);
                    MMA16816(acc1[nt], al, bb1);
                }
            }
        }

        // ---- LIF epilogue (t then t+1), all in registers ----
#pragma unroll
        for (int nt = 0; nt < 4; nt++)
#pragma unroll
            for (int r = 0; r < 4; r++) {
                float bia = (r >> 1) ? bia1 : bia0;
                int idx = nt * 4 + r;
                float i2 = (acc0[nt][r] + bia) * gain;
                v2[idx] += (i2 - v2[idx]) * invtau;
                if (v2[idx] >= th2) { cnt[idx] += 1.0f; v2[idx] = 0.0f; }
                i2 = (acc1[nt][r] + bia) * gain;
                v2[idx] += (i2 - v2[idx]) * invtau;
                if (v2[idx] >= th2) { cnt[idx] += 1.0f; v2[idx] = 0.0f; }
            }
    }

    // ---- pool: sum counts per c2 ----
    float t0 = 0.0f, t1 = 0.0f;
#pragma unroll
    for (int nt = 0; nt < 4; nt++)
#pragma unroll
        for (int r = 0; r < 4; r++) {
            if (r >> 1) t1 += cnt[nt * 4 + r];
            else        t0 += cnt[nt * 4 + r];
        }
    t0 += __shfl_xor_sync(0xffffffffu, t0, 1);
    t0 += __shfl_xor_sync(0xffffffffu, t0, 2);
    t1 += __shfl_xor_sync(0xffffffffu, t1, 1);
    t1 += __shfl_xor_sync(0xffffffffu, t1, 2);
    if (tid4 == 0) {
        atomicAdd(&g_pool[b * NC2 + 16 * j + gid],     t0);   // integer-valued
        atomicAdd(&g_pool[b * NC2 + 16 * j + gid + 8], t1);
    }
}

// ---------------------------------------------------------------------------
// k_fc: pooled = counts / (T*L); logits = pooled @ fc_w.T + fc_b
// ---------------------------------------------------------------------------
__global__ void k_fc(const float* __restrict__ fw,
                     const float* __restrict__ fb,
                     float* __restrict__ out) {
    int tid = threadIdx.x;
    int b = tid >> 2;
    int n = tid & 3;
    const float sc = 1.0f / (float)(TT * LL);
    float s = fb[n];
#pragma unroll
    for (int c = 0; c < NC2; c++)
        s += (g_pool[b * NC2 + c] * sc) * fw[n * NC2 + c];
    out[b * NCLS + n] = s;
}

// ---------------------------------------------------------------------------
extern "C" void kernel_launch(void* const* d_in, const int* in_sizes, int n_in,
                              void* d_out, int out_size) {
    const float* x    = (const float*)d_in[0];
    const float* w1   = (const float*)d_in[1];
    const float* b1   = (const float*)d_in[2];
    const float* w2   = (const float*)d_in[3];
    const float* b2   = (const float*)d_in[4];
    const float* gain = (const float*)d_in[5];
    const float* th1  = (const float*)d_in[6];
    const float* th2  = (const float*)d_in[7];
    const float* fw   = (const float*)d_in[8];
    const float* fb   = (const float*)d_in[9];
    float* out = (float*)d_out;

    cudaFuncSetAttribute(k_snn, cudaFuncAttributeMaxDynamicSharedMemorySize,
                         SNN_SMEM);

    k_pre<<<24, 256>>>(w2);

    dim3 g1(LL / 32, BB);
    k_conv1<<<g1, 256>>>(x, w1, b1, gain, th1);

    k_snn<<<BB * NTILES, 512, SNN_SMEM>>>(b2, gain, th2);

    k_fc<<<1, 256>>>(fw, fb, out);
}

// round 14
// speedup vs baseline: 1.2788x; 1.1086x over previous
#include <cuda_runtime.h>
#include <cuda_fp16.h>
#include <cstdint>

#define BB   64
#define CIN  12
#define LL   4096
#define TT   20
#define NC1  64
#define NC2  64
#define NCLS 4
#define NLT  128                 // l positions per tile
#define NTILES (LL / NLT)        // 32
#define NBP  132                 // padded B rows (130 used)

typedef unsigned long long ull;
typedef unsigned int u32;

// spike bits: 2x u32 per (b,t,l)
__device__ u32 g_s1[BB * TT * LL * 2];
// per (b,c2) spike counts
__device__ float g_pool[BB * NC2];
// fp16 A fragments (K=64 per-tap, single plane), exact mma lane order
__device__ u32 g_Af[6144];

// ---------------- packed f32x2 helpers (conv1) ------------------------------
#define FMA_F32X2(d, a, b, c) \
    asm("fma.rn.f32x2 %0, %1, %2, %3;" : "=l"(d) : "l"(a), "l"(b), "l"(c))
#define PACK_F32X2(out, lo, hi) \
    asm("mov.b64 %0, {%1, %2};" : "=l"(out) : "f"(lo), "f"(hi))
#define UNPACK_F32X2(lo, hi, in) \
    asm("mov.b64 {%0, %1}, %2;" : "=f"(lo), "=f"(hi) : "l"(in))

// mma.sync m16n8k16 f16 x f16 -> f32 (baseline PTX, sm_80+)
#define MMA16816F(d, a, b) \
    asm volatile("mma.sync.aligned.m16n8k16.row.col.f32.f16.f16.f32 " \
        "{%0,%1,%2,%3}, {%4,%5,%6,%7}, {%8,%9}, {%0,%1,%2,%3};" \
        : "+f"((d)[0]), "+f"((d)[1]), "+f"((d)[2]), "+f"((d)[3]) \
        : "r"((a).x), "r"((a).y), "r"((a).z), "r"((a).w), \
          "r"((b).x), "r"((b).y))

// channel permutation matching the multiply-spread decode:
// bits (i, i+16) of half-word mask -> k-positions (2a, 2a+1), a = h*16+i
__device__ __forceinline__ int chan_for_k(int kappa) {
    int a  = kappa >> 1;
    int hh = a >> 4;
    int ii = a & 15;
    return hh * 32 + ii + ((kappa & 1) << 4);
}

// ---------------------------------------------------------------------------
// k_pre: zero pool + build per-tap fp16 A fragments (single plane)
// ---------------------------------------------------------------------------
__global__ void k_pre(const float* __restrict__ w2) {
    int i = blockIdx.x * blockDim.x + threadIdx.x;
    if (i < BB * NC2) g_pool[i] = 0.0f;
    if (i < 6144) {
        int r    = i & 3;
        int idx4 = i >> 2;
        int lane = idx4 & 31;
        int rest = idx4 >> 5;        // (j*3+kk)*4 + s
        int s    = rest & 3;
        int kkj  = rest >> 2;
        int kk   = kkj % 3;
        int j    = kkj / 3;
        int gid  = lane >> 2;
        int t4   = lane & 3;
        int m    = 16 * j + gid + 8 * (r & 1);
        u32 fr = 0;
#pragma unroll
        for (int e = 0; e < 2; e++) {
            int kappa = 16 * s + 2 * t4 + 8 * (r >> 1) + e;
            int c1    = chan_for_k(kappa);
            float wv  = w2[m * (NC1 * 3) + c1 * 3 + kk];
            __half hv = __float2half(wv);
            fr |= (u32)__half_as_ushort(hv) << (16 * e);
        }
        g_Af[i] = fr;
    }
}

// ---------------------------------------------------------------------------
// k_conv1: conv1 + threshold -> bit-packed spikes (TAU1=1 => stateless).
// Sliding-window register reuse over l (R13 version, unchanged).
// ---------------------------------------------------------------------------
__global__ __launch_bounds__(256) void k_conv1(
        const float* __restrict__ x,
        const float* __restrict__ w1,
        const float* __restrict__ b1,
        const float* __restrict__ pgain,
        const float* __restrict__ pth1) {
    __shared__ __align__(16) float s_x[CIN][34][TT];

    const int l0  = blockIdx.x * 32;
    const int b   = blockIdx.y;
    const int tid = threadIdx.x;

    // stage x: (l,t) contiguous per channel -> coalesced
    for (int i = tid; i < CIN * 34 * TT; i += 256) {
        int c   = i / (34 * TT);
        int rem = i % (34 * TT);
        int lx  = rem / TT;
        int t   = rem % TT;
        int gl  = l0 - 1 + lx;
        float v = 0.0f;
        if (gl >= 0 && gl < LL)
            v = x[((size_t)(b * CIN + c) * LL + gl) * TT + t];
        s_x[c][lx][t] = v;
    }

    const int w    = tid >> 5;
    const int lane = tid & 31;
    const int half = w & 1;
    const int pair = w >> 1;
    const int c1   = half * 32 + lane;

    ull wrp[CIN][3];
#pragma unroll
    for (int c = 0; c < CIN; c++)
#pragma unroll
        for (int k = 0; k < 3; k++) {
            float wv = w1[c1 * (CIN * 3) + c * 3 + k];
            PACK_F32X2(wrp[c][k], wv, wv);
        }
    const float bias = b1[c1];
    const float gain = *pgain;
    const float th1  = *pth1;

    __syncthreads();

    // 40 chunks = 5 t-groups x 8 l-chunks, split over 4 warp-pairs
#pragma unroll 1
    for (int chunk = pair; chunk < 40; chunk += 4) {
        const int lc = chunk & 7;
        const int tg = chunk >> 3;
        const int t0 = tg * 4;

        ull acc[4][2];
#pragma unroll
        for (int l = 0; l < 4; l++) { acc[l][0] = 0ull; acc[l][1] = 0ull; }

#pragma unroll
        for (int c = 0; c < CIN; c++) {
            ulonglong2 row[6];
#pragma unroll
            for (int i = 0; i < 6; i++)
                row[i] = *(const ulonglong2*)&s_x[c][lc * 4 + i][t0];
#pragma unroll
            for (int l = 0; l < 4; l++)
#pragma unroll
                for (int k = 0; k < 3; k++) {
                    FMA_F32X2(acc[l][0], row[l + k].x, wrp[c][k], acc[l][0]);
                    FMA_F32X2(acc[l][1], row[l + k].y, wrp[c][k], acc[l][1]);
                }
        }

#pragma unroll
        for (int l = 0; l < 4; l++) {
            float a[4];
            UNPACK_F32X2(a[0], a[1], acc[l][0]);
            UNPACK_F32X2(a[2], a[3], acc[l][1]);
            int gl = l0 + lc * 4 + l;
#pragma unroll
            for (int jj = 0; jj < 4; jj++) {
                float i1 = (a[jj] + bias) * gain;
                u32 m = __ballot_sync(0xffffffffu, i1 >= th1);
                if (lane == 0)
                    g_s1[((size_t)(b * TT + t0 + jj) * LL + gl) * 2 + half] = m;
            }
        }
    }
}

// ---------------------------------------------------------------------------
// k_snn: conv2 via single-plane fp16 mma.sync, 2-timestep batched.
// HMMA count halved vs bf16 hi/lo (fp16 weights carry 11 significand bits;
// spikes are exact in fp16; fp32 accumulate).
// smem u32: Af[0,6144) B[6144, 6144+2*8448)  => 92160 bytes
// ---------------------------------------------------------------------------
#define SNN_SMEM ((6144 + 2 * 8448) * 4)     // 92160 bytes

__global__ __launch_bounds__(512, 1) void k_snn(
        const float* __restrict__ b2,
        const float* __restrict__ pgain,
        const float* __restrict__ pth2) {
    extern __shared__ __align__(16) u32 smw[];
    u32* Ash = smw;
    u32* Bs  = smw + 6144;

    const int tid = threadIdx.x;
    const int b   = blockIdx.x >> 5;
    const int l0  = (blockIdx.x & 31) * NLT;

    // stage A fragments (L2-hot, identical for every CTA)
    for (int i = tid; i < 1536; i += 512)
        ((uint4*)Ash)[i] = ((const uint4*)g_Af)[i];

    const int w    = tid >> 5;
    const int lane = tid & 31;
    const int j    = w & 3;       // m-tile (16 c2 rows)
    const int q    = w >> 2;      // n-quarter (32 l)
    const int gid  = lane >> 2;
    const int tid4 = lane & 3;

    const float gain   = *pgain;
    const float th2    = *pth2;
    const float invtau = 1.0f / 0.9f;
    const float bia0   = b2[16 * j + gid];
    const float bia1   = b2[16 * j + gid + 8];

    // decode task assignment (260 tasks over 512 threads)
    const bool dact = tid < 260;
    int dh = 0, dn = 0;
    bool inrange = false;
    size_t gstep = 0, gaddr = 0;
    if (dact) {
        dh = (tid >= 130) ? 1 : 0;
        dn = tid - 130 * dh;
        int gl  = l0 - 1 + dn;
        inrange = (gl >= 0 && gl < LL);
        if (inrange) {
            gaddr = ((size_t)(b * TT) * LL + gl) * 2 + dh;
            gstep = (size_t)LL * 2;
        }
    }

    float v2[16], cnt[16];
#pragma unroll
    for (int i = 0; i < 16; i++) { v2[i] = 0.0f; cnt[i] = 0.0f; }

    u32 m0n = 0, m1n = 0;
    if (dact && inrange) {
        m0n = g_s1[gaddr];
        m1n = g_s1[gaddr + gstep];
    }

    __syncthreads();

#pragma unroll 1
    for (int tp = 0; tp < TT / 2; tp++) {
        const int p = tp & 1;
        u32* Bq0 = Bs + p * 8448;
        u32* Bq1 = Bq0 + 4224;

        // ---- decode both timesteps of the pair (fp16 1.0 = 0x3C00);
        //      prefetch next pair ----
        u32 mc0 = m0n, mc1 = m1n;
        if (dact && inrange && tp + 1 < TT / 2) {
            m0n = g_s1[gaddr + (size_t)(2 * tp + 2) * gstep];
            m1n = g_s1[gaddr + (size_t)(2 * tp + 3) * gstep];
        }
        if (dact) {
            u32 o[16];
#pragma unroll
            for (int i = 0; i < 16; i++)
                o[i] = ((mc0 >> i) & 0x00010001u) * 0x3C00u;
            u32* r0 = Bq0 + ((2 * dh)     * NBP + dn) * 8;
            u32* r1 = Bq0 + ((2 * dh + 1) * NBP + dn) * 8;
            ((uint4*)r0)[0] = make_uint4(o[0],  o[4],  o[1],  o[5]);
            ((uint4*)r0)[1] = make_uint4(o[2],  o[6],  o[3],  o[7]);
            ((uint4*)r1)[0] = make_uint4(o[8],  o[12], o[9],  o[13]);
            ((uint4*)r1)[1] = make_uint4(o[10], o[14], o[11], o[15]);
#pragma unroll
            for (int i = 0; i < 16; i++)
                o[i] = ((mc1 >> i) & 0x00010001u) * 0x3C00u;
            r0 = Bq1 + ((2 * dh)     * NBP + dn) * 8;
            r1 = Bq1 + ((2 * dh + 1) * NBP + dn) * 8;
            ((uint4*)r0)[0] = make_uint4(o[0],  o[4],  o[1],  o[5]);
            ((uint4*)r0)[1] = make_uint4(o[2],  o[6],  o[3],  o[7]);
            ((uint4*)r1)[0] = make_uint4(o[8],  o[12], o[9],  o[13]);
            ((uint4*)r1)[1] = make_uint4(o[10], o[14], o[11], o[15]);
        }
        __syncthreads();

        // ---- mma: 4 ksteps x 3 taps; each A load feeds both timesteps ----
        float acc0[4][4], acc1[4][4];
#pragma unroll
        for (int nt = 0; nt < 4; nt++)
#pragma unroll
            for (int r = 0; r < 4; r++) { acc0[nt][r] = 0.0f; acc1[nt][r] = 0.0f; }

#pragma unroll
        for (int s = 0; s < 4; s++) {
#pragma unroll
            for (int kk = 0; kk < 3; kk++) {
                int abase = (((j * 3 + kk) * 4 + s) * 32 + lane) * 4;
                uint4 af = *(const uint4*)&Ash[abase];
#pragma unroll
                for (int nt = 0; nt < 4; nt++) {
                    int boff = (s * NBP + q * 32 + nt * 8 + gid + kk) * 8 + tid4 * 2;
                    uint2 bb0 = *(const uint2*)&Bq0[boff];
                    uint2 bb1 = *(const uint2*)&Bq1[boff];
                    MMA16816F(acc0[nt], af, bb0);
                    MMA16816F(acc1[nt], af, bb1);
                }
            }
        }

        // ---- LIF epilogue (t then t+1), all in registers ----
#pragma unroll
        for (int nt = 0; nt < 4; nt++)
#pragma unroll
            for (int r = 0; r < 4; r++) {
                float bia = (r >> 1) ? bia1 : bia0;
                int idx = nt * 4 + r;
                float i2 = (acc0[nt][r] + bia) * gain;
                v2[idx] += (i2 - v2[idx]) * invtau;
                if (v2[idx] >= th2) { cnt[idx] += 1.0f; v2[idx] = 0.0f; }
                i2 = (acc1[nt][r] + bia) * gain;
                v2[idx] += (i2 - v2[idx]) * invtau;
                if (v2[idx] >= th2) { cnt[idx] += 1.0f; v2[idx] = 0.0f; }
            }
    }

    // ---- pool: sum counts per c2 ----
    float t0 = 0.0f, t1 = 0.0f;
#pragma unroll
    for (int nt = 0; nt < 4; nt++)
#pragma unroll
        for (int r = 0; r < 4; r++) {
            if (r >> 1) t1 += cnt[nt * 4 + r];
            else        t0 += cnt[nt * 4 + r];
        }
    t0 += __shfl_xor_sync(0xffffffffu, t0, 1);
    t0 += __shfl_xor_sync(0xffffffffu, t0, 2);
    t1 += __shfl_xor_sync(0xffffffffu, t1, 1);
    t1 += __shfl_xor_sync(0xffffffffu, t1, 2);
    if (tid4 == 0) {
        atomicAdd(&g_pool[b * NC2 + 16 * j + gid],     t0);   // integer-valued
        atomicAdd(&g_pool[b * NC2 + 16 * j + gid + 8], t1);
    }
}

// ---------------------------------------------------------------------------
// k_fc: pooled = counts / (T*L); logits = pooled @ fc_w.T + fc_b
// ---------------------------------------------------------------------------
__global__ void k_fc(const float* __restrict__ fw,
                     const float* __restrict__ fb,
                     float* __restrict__ out) {
    int tid = threadIdx.x;
    int b = tid >> 2;
    int n = tid & 3;
    const float sc = 1.0f / (float)(TT * LL);
    float s = fb[n];
#pragma unroll
    for (int c = 0; c < NC2; c++)
        s += (g_pool[b * NC2 + c] * sc) * fw[n * NC2 + c];
    out[b * NCLS + n] = s;
}

// ---------------------------------------------------------------------------
extern "C" void kernel_launch(void* const* d_in, const int* in_sizes, int n_in,
                              void* d_out, int out_size) {
    const float* x    = (const float*)d_in[0];
    const float* w1   = (const float*)d_in[1];
    const float* b1   = (const float*)d_in[2];
    const float* w2   = (const float*)d_in[3];
    const float* b2   = (const float*)d_in[4];
    const float* gain = (const float*)d_in[5];
    const float* th1  = (const float*)d_in[6];
    const float* th2  = (const float*)d_in[7];
    const float* fw   = (const float*)d_in[8];
    const float* fb   = (const float*)d_in[9];
    float* out = (float*)d_out;

    cudaFuncSetAttribute(k_snn, cudaFuncAttributeMaxDynamicSharedMemorySize,
                         SNN_SMEM);

    k_pre<<<24, 256>>>(w2);

    dim3 g1(LL / 32, BB);
    k_conv1<<<g1, 256>>>(x, w1, b1, gain, th1);

    k_snn<<<BB * NTILES, 512, SNN_SMEM>>>(b2, gain, th2);

    k_fc<<<1, 256>>>(fw, fb, out);
}

// round 15
// speedup vs baseline: 1.3367x; 1.0453x over previous
#include <cuda_runtime.h>
#include <cuda_fp16.h>
#include <cstdint>

#define BB   64
#define CIN  12
#define LL   4096
#define TT   20
#define NC1  64
#define NC2  64
#define NCLS 4
#define NLT  128                 // l positions per tile
#define NTILES (LL / NLT)        // 32
#define NBP  132                 // padded B rows (130 used)

typedef unsigned long long ull;
typedef unsigned int u32;

// spike bits: 2x u32 per (b,t,l)
__device__ u32 g_s1[BB * TT * LL * 2];
// per (b,c2) spike counts
__device__ float g_pool[BB * NC2];
// fp16 A fragments (K=64 per-tap, single plane), exact mma lane order
__device__ u32 g_Af[6144];

// ---------------- packed f32x2 helpers (conv1) ------------------------------
#define FMA_F32X2(d, a, b, c) \
    asm("fma.rn.f32x2 %0, %1, %2, %3;" : "=l"(d) : "l"(a), "l"(b), "l"(c))
#define PACK_F32X2(out, lo, hi) \
    asm("mov.b64 %0, {%1, %2};" : "=l"(out) : "f"(lo), "f"(hi))
#define UNPACK_F32X2(lo, hi, in) \
    asm("mov.b64 {%0, %1}, %2;" : "=f"(lo), "=f"(hi) : "l"(in))

// mma.sync m16n8k16 f16 x f16 -> f32 (baseline PTX, sm_80+)
#define MMA16816F(d, a, b) \
    asm volatile("mma.sync.aligned.m16n8k16.row.col.f32.f16.f16.f32 " \
        "{%0,%1,%2,%3}, {%4,%5,%6,%7}, {%8,%9}, {%0,%1,%2,%3};" \
        : "+f"((d)[0]), "+f"((d)[1]), "+f"((d)[2]), "+f"((d)[3]) \
        : "r"((a).x), "r"((a).y), "r"((a).z), "r"((a).w), \
          "r"((b).x), "r"((b).y))

// channel permutation matching the multiply-spread decode:
// bits (i, i+16) of half-word mask -> k-positions (2a, 2a+1), a = h*16+i
__device__ __forceinline__ int chan_for_k(int kappa) {
    int a  = kappa >> 1;
    int hh = a >> 4;
    int ii = a & 15;
    return hh * 32 + ii + ((kappa & 1) << 4);
}

// ---------------------------------------------------------------------------
// k_pre: zero pool + build per-tap fp16 A fragments (single plane)
// ---------------------------------------------------------------------------
__global__ void k_pre(const float* __restrict__ w2) {
    int i = blockIdx.x * blockDim.x + threadIdx.x;
    if (i < BB * NC2) g_pool[i] = 0.0f;
    if (i < 6144) {
        int r    = i & 3;
        int idx4 = i >> 2;
        int lane = idx4 & 31;
        int rest = idx4 >> 5;        // (j*3+kk)*4 + s
        int s    = rest & 3;
        int kkj  = rest >> 2;
        int kk   = kkj % 3;
        int j    = kkj / 3;
        int gid  = lane >> 2;
        int t4   = lane & 3;
        int m    = 16 * j + gid + 8 * (r & 1);
        u32 fr = 0;
#pragma unroll
        for (int e = 0; e < 2; e++) {
            int kappa = 16 * s + 2 * t4 + 8 * (r >> 1) + e;
            int c1    = chan_for_k(kappa);
            float wv  = w2[m * (NC1 * 3) + c1 * 3 + kk];
            __half hv = __float2half(wv);
            fr |= (u32)__half_as_ushort(hv) << (16 * e);
        }
        g_Af[i] = fr;
    }
}

// ---------------------------------------------------------------------------
// k_conv1: conv1 + threshold -> bit-packed spikes (TAU1=1 => stateless).
// Sliding-window register reuse over l (R13 version, unchanged).
// ---------------------------------------------------------------------------
__global__ __launch_bounds__(256) void k_conv1(
        const float* __restrict__ x,
        const float* __restrict__ w1,
        const float* __restrict__ b1,
        const float* __restrict__ pgain,
        const float* __restrict__ pth1) {
    __shared__ __align__(16) float s_x[CIN][34][TT];

    const int l0  = blockIdx.x * 32;
    const int b   = blockIdx.y;
    const int tid = threadIdx.x;

    for (int i = tid; i < CIN * 34 * TT; i += 256) {
        int c   = i / (34 * TT);
        int rem = i % (34 * TT);
        int lx  = rem / TT;
        int t   = rem % TT;
        int gl  = l0 - 1 + lx;
        float v = 0.0f;
        if (gl >= 0 && gl < LL)
            v = x[((size_t)(b * CIN + c) * LL + gl) * TT + t];
        s_x[c][lx][t] = v;
    }

    const int w    = tid >> 5;
    const int lane = tid & 31;
    const int half = w & 1;
    const int pair = w >> 1;
    const int c1   = half * 32 + lane;

    ull wrp[CIN][3];
#pragma unroll
    for (int c = 0; c < CIN; c++)
#pragma unroll
        for (int k = 0; k < 3; k++) {
            float wv = w1[c1 * (CIN * 3) + c * 3 + k];
            PACK_F32X2(wrp[c][k], wv, wv);
        }
    const float bias = b1[c1];
    const float gain = *pgain;
    const float th1  = *pth1;

    __syncthreads();

#pragma unroll 1
    for (int chunk = pair; chunk < 40; chunk += 4) {
        const int lc = chunk & 7;
        const int tg = chunk >> 3;
        const int t0 = tg * 4;

        ull acc[4][2];
#pragma unroll
        for (int l = 0; l < 4; l++) { acc[l][0] = 0ull; acc[l][1] = 0ull; }

#pragma unroll
        for (int c = 0; c < CIN; c++) {
            ulonglong2 row[6];
#pragma unroll
            for (int i = 0; i < 6; i++)
                row[i] = *(const ulonglong2*)&s_x[c][lc * 4 + i][t0];
#pragma unroll
            for (int l = 0; l < 4; l++)
#pragma unroll
                for (int k = 0; k < 3; k++) {
                    FMA_F32X2(acc[l][0], row[l + k].x, wrp[c][k], acc[l][0]);
                    FMA_F32X2(acc[l][1], row[l + k].y, wrp[c][k], acc[l][1]);
                }
        }

#pragma unroll
        for (int l = 0; l < 4; l++) {
            float a[4];
            UNPACK_F32X2(a[0], a[1], acc[l][0]);
            UNPACK_F32X2(a[2], a[3], acc[l][1]);
            int gl = l0 + lc * 4 + l;
#pragma unroll
            for (int jj = 0; jj < 4; jj++) {
                float i1 = (a[jj] + bias) * gain;
                u32 m = __ballot_sync(0xffffffffu, i1 >= th1);
                if (lane == 0)
                    g_s1[((size_t)(b * TT + t0 + jj) * LL + gl) * 2 + half] = m;
            }
        }
    }
}

// ---------------------------------------------------------------------------
// decode helper: spike words for one t-pair -> fp16 fragment tile
// ---------------------------------------------------------------------------
__device__ __forceinline__ void decode_pair(u32* Bpair, u32 mc0, u32 mc1,
                                            int dh, int dn) {
    u32 o[16];
#pragma unroll
    for (int i = 0; i < 16; i++)
        o[i] = ((mc0 >> i) & 0x00010001u) * 0x3C00u;
    u32* r0 = Bpair + ((2 * dh)     * NBP + dn) * 8;
    u32* r1 = Bpair + ((2 * dh + 1) * NBP + dn) * 8;
    ((uint4*)r0)[0] = make_uint4(o[0],  o[4],  o[1],  o[5]);
    ((uint4*)r0)[1] = make_uint4(o[2],  o[6],  o[3],  o[7]);
    ((uint4*)r1)[0] = make_uint4(o[8],  o[12], o[9],  o[13]);
    ((uint4*)r1)[1] = make_uint4(o[10], o[14], o[11], o[15]);
#pragma unroll
    for (int i = 0; i < 16; i++)
        o[i] = ((mc1 >> i) & 0x00010001u) * 0x3C00u;
    r0 = Bpair + 4224 + ((2 * dh)     * NBP + dn) * 8;
    r1 = Bpair + 4224 + ((2 * dh + 1) * NBP + dn) * 8;
    ((uint4*)r0)[0] = make_uint4(o[0],  o[4],  o[1],  o[5]);
    ((uint4*)r0)[1] = make_uint4(o[2],  o[6],  o[3],  o[7]);
    ((uint4*)r1)[0] = make_uint4(o[8],  o[12], o[9],  o[13]);
    ((uint4*)r1)[1] = make_uint4(o[10], o[14], o[11], o[15]);
}

// ---------------------------------------------------------------------------
// k_snn: conv2 via single-plane fp16 mma.sync, 2-timestep batched,
// SOFTWARE-PIPELINED: decode(tp+1) issues between MMA(tp) and LIF(tp) so its
// ALU/STS stream dual-issues while the tensor unit drains (was serialized
// before the barrier with the tensor pipe idle). One barrier per pair.
// smem u32: Af[0,6144) B[6144, 6144+2*8448)  => 92160 bytes
// ---------------------------------------------------------------------------
#define SNN_SMEM ((6144 + 2 * 8448) * 4)     // 92160 bytes

__global__ __launch_bounds__(512, 1) void k_snn(
        const float* __restrict__ b2,
        const float* __restrict__ pgain,
        const float* __restrict__ pth2) {
    extern __shared__ __align__(16) u32 smw[];
    u32* Ash = smw;
    u32* Bs  = smw + 6144;

    const int tid = threadIdx.x;
    const int b   = blockIdx.x >> 5;
    const int l0  = (blockIdx.x & 31) * NLT;

    // stage A fragments (L2-hot, identical for every CTA)
    for (int i = tid; i < 1536; i += 512)
        ((uint4*)Ash)[i] = ((const uint4*)g_Af)[i];

    const int w    = tid >> 5;
    const int lane = tid & 31;
    const int j    = w & 3;       // m-tile (16 c2 rows)
    const int q    = w >> 2;      // n-quarter (32 l)
    const int gid  = lane >> 2;
    const int tid4 = lane & 3;

    const float gain   = *pgain;
    const float th2    = *pth2;
    const float invtau = 1.0f / 0.9f;
    const float bia0   = b2[16 * j + gid];
    const float bia1   = b2[16 * j + gid + 8];

    // decode task assignment (260 tasks over 512 threads)
    const bool dact = tid < 260;
    int dh = 0, dn = 0;
    bool inrange = false;
    size_t gstep = 0, gaddr = 0;
    if (dact) {
        dh = (tid >= 130) ? 1 : 0;
        dn = tid - 130 * dh;
        int gl  = l0 - 1 + dn;
        inrange = (gl >= 0 && gl < LL);
        if (inrange) {
            gaddr = ((size_t)(b * TT) * LL + gl) * 2 + dh;
            gstep = (size_t)LL * 2;
        }
    }

    float v2[16], cnt[16];
#pragma unroll
    for (int i = 0; i < 16; i++) { v2[i] = 0.0f; cnt[i] = 0.0f; }

    // ---- prologue: decode pair 0 into buf 0; prefetch pair-1 words ----
    u32 mA = 0, mB = 0;
    if (dact && inrange) {
        u32 p00 = g_s1[gaddr];
        u32 p01 = g_s1[gaddr + gstep];
        decode_pair(Bs, p00, p01, dh, dn);
        mA = g_s1[gaddr + 2 * gstep];
        mB = g_s1[gaddr + 3 * gstep];
    } else if (dact) {
        decode_pair(Bs, 0u, 0u, dh, dn);
    }
    __syncthreads();

#pragma unroll 1
    for (int tp = 0; tp < TT / 2; tp++) {
        const int p = tp & 1;
        u32* Bq0 = Bs + p * 8448;
        u32* Bq1 = Bq0 + 4224;

        // ---- issue MMA(tp): 4 ksteps x 3 taps; A load feeds both t ----
        float acc0[4][4], acc1[4][4];
#pragma unroll
        for (int nt = 0; nt < 4; nt++)
#pragma unroll
            for (int r = 0; r < 4; r++) { acc0[nt][r] = 0.0f; acc1[nt][r] = 0.0f; }

#pragma unroll
        for (int s = 0; s < 4; s++) {
#pragma unroll
            for (int kk = 0; kk < 3; kk++) {
                int abase = (((j * 3 + kk) * 4 + s) * 32 + lane) * 4;
                uint4 af = *(const uint4*)&Ash[abase];
#pragma unroll
                for (int nt = 0; nt < 4; nt++) {
                    int boff = (s * NBP + q * 32 + nt * 8 + gid + kk) * 8 + tid4 * 2;
                    uint2 bb0 = *(const uint2*)&Bq0[boff];
                    uint2 bb1 = *(const uint2*)&Bq1[boff];
                    MMA16816F(acc0[nt], af, bb0);
                    MMA16816F(acc1[nt], af, bb1);
                }
            }
        }

        // ---- decode(tp+1) into buf p^1 — overlaps tensor drain ----
        if (dact && tp + 1 < TT / 2) {
            decode_pair(Bs + (p ^ 1) * 8448, mA, mB, dh, dn);
            if (inrange && tp + 2 < TT / 2) {
                mA = g_s1[gaddr + (size_t)(2 * tp + 4) * gstep];
                mB = g_s1[gaddr + (size_t)(2 * tp + 5) * gstep];
            }
        }

        // ---- LIF epilogue (t then t+1), all in registers ----
#pragma unroll
        for (int nt = 0; nt < 4; nt++)
#pragma unroll
            for (int r = 0; r < 4; r++) {
                float bia = (r >> 1) ? bia1 : bia0;
                int idx = nt * 4 + r;
                float i2 = (acc0[nt][r] + bia) * gain;
                v2[idx] += (i2 - v2[idx]) * invtau;
                if (v2[idx] >= th2) { cnt[idx] += 1.0f; v2[idx] = 0.0f; }
                i2 = (acc1[nt][r] + bia) * gain;
                v2[idx] += (i2 - v2[idx]) * invtau;
                if (v2[idx] >= th2) { cnt[idx] += 1.0f; v2[idx] = 0.0f; }
            }

        __syncthreads();   // publish buf p^1; protect buf p for next decode
    }

    // ---- pool: sum counts per c2 ----
    float t0 = 0.0f, t1 = 0.0f;
#pragma unroll
    for (int nt = 0; nt < 4; nt++)
#pragma unroll
        for (int r = 0; r < 4; r++) {
            if (r >> 1) t1 += cnt[nt * 4 + r];
            else        t0 += cnt[nt * 4 + r];
        }
    t0 += __shfl_xor_sync(0xffffffffu, t0, 1);
    t0 += __shfl_xor_sync(0xffffffffu, t0, 2);
    t1 += __shfl_xor_sync(0xffffffffu, t1, 1);
    t1 += __shfl_xor_sync(0xffffffffu, t1, 2);
    if (tid4 == 0) {
        atomicAdd(&g_pool[b * NC2 + 16 * j + gid],     t0);   // integer-valued
        atomicAdd(&g_pool[b * NC2 + 16 * j + gid + 8], t1);
    }
}

// ---------------------------------------------------------------------------
// k_fc: pooled = counts / (T*L); logits = pooled @ fc_w.T + fc_b
// ---------------------------------------------------------------------------
__global__ void k_fc(const float* __restrict__ fw,
                     const float* __restrict__ fb,
                     float* __restrict__ out) {
    int tid = threadIdx.x;
    int b = tid >> 2;
    int n = tid & 3;
    const float sc = 1.0f / (float)(TT * LL);
    float s = fb[n];
#pragma unroll
    for (int c = 0; c < NC2; c++)
        s += (g_pool[b * NC2 + c] * sc) * fw[n * NC2 + c];
    out[b * NCLS + n] = s;
}

// ---------------------------------------------------------------------------
extern "C" void kernel_launch(void* const* d_in, const int* in_sizes, int n_in,
                              void* d_out, int out_size) {
    const float* x    = (const float*)d_in[0];
    const float* w1   = (const float*)d_in[1];
    const float* b1   = (const float*)d_in[2];
    const float* w2   = (const float*)d_in[3];
    const float* b2   = (const float*)d_in[4];
    const float* gain = (const float*)d_in[5];
    const float* th1  = (const float*)d_in[6];
    const float* th2  = (const float*)d_in[7];
    const float* fw   = (const float*)d_in[8];
    const float* fb   = (const float*)d_in[9];
    float* out = (float*)d_out;

    cudaFuncSetAttribute(k_snn, cudaFuncAttributeMaxDynamicSharedMemorySize,
                         SNN_SMEM);

    k_pre<<<24, 256>>>(w2);

    dim3 g1(LL / 32, BB);
    k_conv1<<<g1, 256>>>(x, w1, b1, gain, th1);

    k_snn<<<BB * NTILES, 512, SNN_SMEM>>>(b2, gain, th2);

    k_fc<<<1, 256>>>(fw, fb, out);
}

// round 16
// speedup vs baseline: 1.4241x; 1.0654x over previous
#include <cuda_runtime.h>
#include <cuda_fp16.h>
#include <cstdint>

#define BB   64
#define CIN  12
#define LL   4096
#define TT   20
#define NC1  64
#define NC2  64
#define NCLS 4
#define NLT  64                  // l positions per k_snn tile
#define NTILES (LL / NLT)        // 64
#define NBR  66                  // B rows per k-step (l0-1 .. l0+64)

typedef unsigned long long ull;
typedef unsigned int u32;

// spike bits: 2x u32 per (b,t,l)
__device__ u32 g_s1[BB * TT * LL * 2];
// per (b,c2) spike counts
__device__ float g_pool[BB * NC2];
// fp16 A fragments (K=64 per-tap, single plane), exact mma lane order
__device__ u32 g_Af[6144];

// ---------------- packed f32x2 helpers (conv1) ------------------------------
#define FMA_F32X2(d, a, b, c) \
    asm("fma.rn.f32x2 %0, %1, %2, %3;" : "=l"(d) : "l"(a), "l"(b), "l"(c))
#define PACK_F32X2(out, lo, hi) \
    asm("mov.b64 %0, {%1, %2};" : "=l"(out) : "f"(lo), "f"(hi))
#define UNPACK_F32X2(lo, hi, in) \
    asm("mov.b64 {%0, %1}, %2;" : "=f"(lo), "=f"(hi) : "l"(in))

// mma.sync m16n8k16 f16 x f16 -> f32 (baseline PTX, sm_80+)
#define MMA16816F(d, a, b) \
    asm volatile("mma.sync.aligned.m16n8k16.row.col.f32.f16.f16.f32 " \
        "{%0,%1,%2,%3}, {%4,%5,%6,%7}, {%8,%9}, {%0,%1,%2,%3};" \
        : "+f"((d)[0]), "+f"((d)[1]), "+f"((d)[2]), "+f"((d)[3]) \
        : "r"((a).x), "r"((a).y), "r"((a).z), "r"((a).w), \
          "r"((b).x), "r"((b).y))

// channel permutation matching the multiply-spread decode:
// bits (i, i+16) of half-word mask -> k-positions (2a, 2a+1), a = h*16+i
__device__ __forceinline__ int chan_for_k(int kappa) {
    int a  = kappa >> 1;
    int hh = a >> 4;
    int ii = a & 15;
    return hh * 32 + ii + ((kappa & 1) << 4);
}

// ---------------------------------------------------------------------------
// k_pre: zero pool + build per-tap fp16 A fragments (single plane)
// ---------------------------------------------------------------------------
__global__ void k_pre(const float* __restrict__ w2) {
    int i = blockIdx.x * blockDim.x + threadIdx.x;
    if (i < BB * NC2) g_pool[i] = 0.0f;
    if (i < 6144) {
        int r    = i & 3;
        int idx4 = i >> 2;
        int lane = idx4 & 31;
        int rest = idx4 >> 5;        // (j*3+kk)*4 + s
        int s    = rest & 3;
        int kkj  = rest >> 2;
        int kk   = kkj % 3;
        int j    = kkj / 3;
        int gid  = lane >> 2;
        int t4   = lane & 3;
        int m    = 16 * j + gid + 8 * (r & 1);
        u32 fr = 0;
#pragma unroll
        for (int e = 0; e < 2; e++) {
            int kappa = 16 * s + 2 * t4 + 8 * (r >> 1) + e;
            int c1    = chan_for_k(kappa);
            float wv  = w2[m * (NC1 * 3) + c1 * 3 + kk];
            __half hv = __float2half(wv);
            fr |= (u32)__half_as_ushort(hv) << (16 * e);
        }
        g_Af[i] = fr;
    }
}

// ---------------------------------------------------------------------------
// k_conv1: conv1 + threshold -> bit-packed spikes (TAU1=1 => stateless).
// Sliding-window register reuse over l (R13 version, unchanged).
// ---------------------------------------------------------------------------
__global__ __launch_bounds__(256) void k_conv1(
        const float* __restrict__ x,
        const float* __restrict__ w1,
        const float* __restrict__ b1,
        const float* __restrict__ pgain,
        const float* __restrict__ pth1) {
    __shared__ __align__(16) float s_x[CIN][34][TT];

    const int l0  = blockIdx.x * 32;
    const int b   = blockIdx.y;
    const int tid = threadIdx.x;

    for (int i = tid; i < CIN * 34 * TT; i += 256) {
        int c   = i / (34 * TT);
        int rem = i % (34 * TT);
        int lx  = rem / TT;
        int t   = rem % TT;
        int gl  = l0 - 1 + lx;
        float v = 0.0f;
        if (gl >= 0 && gl < LL)
            v = x[((size_t)(b * CIN + c) * LL + gl) * TT + t];
        s_x[c][lx][t] = v;
    }

    const int w    = tid >> 5;
    const int lane = tid & 31;
    const int half = w & 1;
    const int pair = w >> 1;
    const int c1   = half * 32 + lane;

    ull wrp[CIN][3];
#pragma unroll
    for (int c = 0; c < CIN; c++)
#pragma unroll
        for (int k = 0; k < 3; k++) {
            float wv = w1[c1 * (CIN * 3) + c * 3 + k];
            PACK_F32X2(wrp[c][k], wv, wv);
        }
    const float bias = b1[c1];
    const float gain = *pgain;
    const float th1  = *pth1;

    __syncthreads();

#pragma unroll 1
    for (int chunk = pair; chunk < 40; chunk += 4) {
        const int lc = chunk & 7;
        const int tg = chunk >> 3;
        const int t0 = tg * 4;

        ull acc[4][2];
#pragma unroll
        for (int l = 0; l < 4; l++) { acc[l][0] = 0ull; acc[l][1] = 0ull; }

#pragma unroll
        for (int c = 0; c < CIN; c++) {
            ulonglong2 row[6];
#pragma unroll
            for (int i = 0; i < 6; i++)
                row[i] = *(const ulonglong2*)&s_x[c][lc * 4 + i][t0];
#pragma unroll
            for (int l = 0; l < 4; l++)
#pragma unroll
                for (int k = 0; k < 3; k++) {
                    FMA_F32X2(acc[l][0], row[l + k].x, wrp[c][k], acc[l][0]);
                    FMA_F32X2(acc[l][1], row[l + k].y, wrp[c][k], acc[l][1]);
                }
        }

#pragma unroll
        for (int l = 0; l < 4; l++) {
            float a[4];
            UNPACK_F32X2(a[0], a[1], acc[l][0]);
            UNPACK_F32X2(a[2], a[3], acc[l][1]);
            int gl = l0 + lc * 4 + l;
#pragma unroll
            for (int jj = 0; jj < 4; jj++) {
                float i1 = (a[jj] + bias) * gain;
                u32 m = __ballot_sync(0xffffffffu, i1 >= th1);
                if (lane == 0)
                    g_s1[((size_t)(b * TT + t0 + jj) * LL + gl) * 2 + half] = m;
            }
        }
    }
}

// ---------------------------------------------------------------------------
// decode helper: spike words for one t -> fp16 fragment tile (64-l tile)
// B layout: [s][row NBR][8 u32]; s = 2*dh covers kappa 32h..+15, s=2*dh+1 next
// ---------------------------------------------------------------------------
__device__ __forceinline__ void decode_t(u32* Bt, u32 mc, int dh, int dn) {
    u32 o[16];
#pragma unroll
    for (int i = 0; i < 16; i++)
        o[i] = ((mc >> i) & 0x00010001u) * 0x3C00u;
    u32* r0 = Bt + ((2 * dh)     * NBR + dn) * 8;
    u32* r1 = Bt + ((2 * dh + 1) * NBR + dn) * 8;
    ((uint4*)r0)[0] = make_uint4(o[0],  o[4],  o[1],  o[5]);
    ((uint4*)r0)[1] = make_uint4(o[2],  o[6],  o[3],  o[7]);
    ((uint4*)r1)[0] = make_uint4(o[8],  o[12], o[9],  o[13]);
    ((uint4*)r1)[1] = make_uint4(o[10], o[14], o[11], o[15]);
}

// ---------------------------------------------------------------------------
// k_snn: conv2 via single-plane fp16 mma.sync.
// 256 threads / 64-l tile, 2 CTAs per SM (occupancy hides barrier/LIF
// bubbles). A fragments live in REGISTERS (48 regs, loaded once from L2-hot
// g_Af) -> zero A smem traffic. Software-pipelined decode as in R15.
// smem: 2 x 2112 u32 B buffers = 16896 bytes.
// ---------------------------------------------------------------------------
#define SNN_SMEM (2 * 2112 * 4)

__global__ __launch_bounds__(256, 2) void k_snn(
        const float* __restrict__ b2,
        const float* __restrict__ pgain,
        const float* __restrict__ pth2) {
    extern __shared__ __align__(16) u32 Bs[];

    const int tid = threadIdx.x;
    const int b   = blockIdx.x >> 6;          // / NTILES
    const int l0  = (blockIdx.x & 63) * NLT;

    const int w    = tid >> 5;
    const int lane = tid & 31;
    const int j    = w & 3;       // m-tile (16 c2 rows)
    const int q    = (w >> 2) & 1;// n-half (32 l)
    const int gid  = lane >> 2;
    const int tid4 = lane & 3;

    // A fragments -> registers (L2-hot; identical for every CTA)
    uint4 afr[12];
#pragma unroll
    for (int s = 0; s < 4; s++)
#pragma unroll
        for (int kk = 0; kk < 3; kk++)
            afr[s * 3 + kk] =
                *(const uint4*)&g_Af[(((j * 3 + kk) * 4 + s) * 32 + lane) * 4];

    const float gain   = *pgain;
    const float th2    = *pth2;
    const float invtau = 1.0f / 0.9f;
    const float bia0   = b2[16 * j + gid];
    const float bia1   = b2[16 * j + gid + 8];

    // decode task assignment (132 tasks over 256 threads)
    const bool dact = tid < 132;
    int dh = 0, dn = 0;
    bool inrange = false;
    size_t gstep = 0, gaddr = 0;
    if (dact) {
        dh = (tid >= NBR) ? 1 : 0;
        dn = tid - NBR * dh;
        int gl  = l0 - 1 + dn;
        inrange = (gl >= 0 && gl < LL);
        if (inrange) {
            gaddr = ((size_t)(b * TT) * LL + gl) * 2 + dh;
            gstep = (size_t)LL * 2;
        }
    }

    float v2[16], cnt[16];
#pragma unroll
    for (int i = 0; i < 16; i++) { v2[i] = 0.0f; cnt[i] = 0.0f; }

    // ---- prologue: decode t=0 into buf 0; prefetch t=1 mask ----
    u32 mN = 0;
    if (dact) {
        u32 m0 = inrange ? g_s1[gaddr] : 0u;
        decode_t(Bs, m0, dh, dn);
        if (inrange) mN = g_s1[gaddr + gstep];
    }
    __syncthreads();

#pragma unroll 1
    for (int t = 0; t < TT; t++) {
        const int p = t & 1;
        u32* Bp = Bs + p * 2112;

        // ---- MMA(t): s outer, kk, nt — same accumulation order as R14/15 ----
        float acc[4][4];
#pragma unroll
        for (int nt = 0; nt < 4; nt++)
#pragma unroll
            for (int r = 0; r < 4; r++) acc[nt][r] = 0.0f;

#pragma unroll
        for (int s = 0; s < 4; s++) {
#pragma unroll
            for (int kk = 0; kk < 3; kk++) {
                uint4 af = afr[s * 3 + kk];
#pragma unroll
                for (int nt = 0; nt < 4; nt++) {
                    int boff = (s * NBR + q * 32 + nt * 8 + gid + kk) * 8 + tid4 * 2;
                    uint2 bb = *(const uint2*)&Bp[boff];
                    MMA16816F(acc[nt], af, bb);
                }
            }
        }

        // ---- decode(t+1) into buf p^1 — overlaps tensor drain ----
        if (dact && t + 1 < TT) {
            decode_t(Bs + (p ^ 1) * 2112, mN, dh, dn);
            if (inrange && t + 2 < TT)
                mN = g_s1[gaddr + (size_t)(t + 2) * gstep];
        }

        // ---- LIF epilogue, all in registers ----
#pragma unroll
        for (int nt = 0; nt < 4; nt++)
#pragma unroll
            for (int r = 0; r < 4; r++) {
                float bia = (r >> 1) ? bia1 : bia0;
                int idx = nt * 4 + r;
                float i2 = (acc[nt][r] + bia) * gain;
                v2[idx] += (i2 - v2[idx]) * invtau;
                if (v2[idx] >= th2) { cnt[idx] += 1.0f; v2[idx] = 0.0f; }
            }

        __syncthreads();   // publish buf p^1; protect buf p for next decode
    }

    // ---- pool: sum counts per c2 ----
    float t0 = 0.0f, t1 = 0.0f;
#pragma unroll
    for (int nt = 0; nt < 4; nt++)
#pragma unroll
        for (int r = 0; r < 4; r++) {
            if (r >> 1) t1 += cnt[nt * 4 + r];
            else        t0 += cnt[nt * 4 + r];
        }
    t0 += __shfl_xor_sync(0xffffffffu, t0, 1);
    t0 += __shfl_xor_sync(0xffffffffu, t0, 2);
    t1 += __shfl_xor_sync(0xffffffffu, t1, 1);
    t1 += __shfl_xor_sync(0xffffffffu, t1, 2);
    if (tid4 == 0) {
        atomicAdd(&g_pool[b * NC2 + 16 * j + gid],     t0);   // integer-valued
        atomicAdd(&g_pool[b * NC2 + 16 * j + gid + 8], t1);
    }
}

// ---------------------------------------------------------------------------
// k_fc: pooled = counts / (T*L); logits = pooled @ fc_w.T + fc_b
// ---------------------------------------------------------------------------
__global__ void k_fc(const float* __restrict__ fw,
                     const float* __restrict__ fb,
                     float* __restrict__ out) {
    int tid = threadIdx.x;
    int b = tid >> 2;
    int n = tid & 3;
    const float sc = 1.0f / (float)(TT * LL);
    float s = fb[n];
#pragma unroll
    for (int c = 0; c < NC2; c++)
        s += (g_pool[b * NC2 + c] * sc) * fw[n * NC2 + c];
    out[b * NCLS + n] = s;
}

// ---------------------------------------------------------------------------
extern "C" void kernel_launch(void* const* d_in, const int* in_sizes, int n_in,
                              void* d_out, int out_size) {
    const float* x    = (const float*)d_in[0];
    const float* w1   = (const float*)d_in[1];
    const float* b1   = (const float*)d_in[2];
    const float* w2   = (const float*)d_in[3];
    const float* b2   = (const float*)d_in[4];
    const float* gain = (const float*)d_in[5];
    const float* th1  = (const float*)d_in[6];
    const float* th2  = (const float*)d_in[7];
    const float* fw   = (const float*)d_in[8];
    const float* fb   = (const float*)d_in[9];
    float* out = (float*)d_out;

    cudaFuncSetAttribute(k_snn, cudaFuncAttributeMaxDynamicSharedMemorySize,
                         SNN_SMEM);

    k_pre<<<24, 256>>>(w2);

    dim3 g1(LL / 32, BB);
    k_conv1<<<g1, 256>>>(x, w1, b1, gain, th1);

    k_snn<<<BB * NTILES, 256, SNN_SMEM>>>(b2, gain, th2);

    k_fc<<<1, 256>>>(fw, fb, out);
}

// round 17
// speedup vs baseline: 1.4436x; 1.0137x over previous
#include <cuda_runtime.h>
#include <cuda_fp16.h>
#include <cstdint>

#define BB   64
#define CIN  12
#define LL   4096
#define TT   20
#define NC1  64
#define NC2  64
#define NCLS 4
#define NLT  64                  // l positions per k_snn tile
#define NTILES (LL / NLT)        // 64
#define NBR  66                  // B rows per k-step (l0-1 .. l0+64)

typedef unsigned long long ull;
typedef unsigned int u32;

// spike bits: 2x u32 per (b,t,l)
__device__ u32 g_s1[BB * TT * LL * 2];
// per (b,c2) spike counts
__device__ float g_pool[BB * NC2];
// fp16 A fragments (K=64 per-tap, single plane), exact mma lane order
__device__ u32 g_Af[6144];

// ---------------- packed f32x2 helpers (conv1) ------------------------------
#define FMA_F32X2(d, a, b, c) \
    asm("fma.rn.f32x2 %0, %1, %2, %3;" : "=l"(d) : "l"(a), "l"(b), "l"(c))
#define PACK_F32X2(out, lo, hi) \
    asm("mov.b64 %0, {%1, %2};" : "=l"(out) : "f"(lo), "f"(hi))
#define UNPACK_F32X2(lo, hi, in) \
    asm("mov.b64 {%0, %1}, %2;" : "=f"(lo), "=f"(hi) : "l"(in))

// mma.sync m16n8k16 f16 x f16 -> f32 (baseline PTX, sm_80+)
#define MMA16816F(d, a, b) \
    asm volatile("mma.sync.aligned.m16n8k16.row.col.f32.f16.f16.f32 " \
        "{%0,%1,%2,%3}, {%4,%5,%6,%7}, {%8,%9}, {%0,%1,%2,%3};" \
        : "+f"((d)[0]), "+f"((d)[1]), "+f"((d)[2]), "+f"((d)[3]) \
        : "r"((a).x), "r"((a).y), "r"((a).z), "r"((a).w), \
          "r"((b).x), "r"((b).y))

// channel permutation matching the multiply-spread decode:
// bits (i, i+16) of half-word mask -> k-positions (2a, 2a+1), a = h*16+i
__device__ __forceinline__ int chan_for_k(int kappa) {
    int a  = kappa >> 1;
    int hh = a >> 4;
    int ii = a & 15;
    return hh * 32 + ii + ((kappa & 1) << 4);
}

// ---------------------------------------------------------------------------
// k_pre: zero pool + build per-tap fp16 A fragments (single plane)
// ---------------------------------------------------------------------------
__global__ void k_pre(const float* __restrict__ w2) {
    int i = blockIdx.x * blockDim.x + threadIdx.x;
    if (i < BB * NC2) g_pool[i] = 0.0f;
    if (i < 6144) {
        int r    = i & 3;
        int idx4 = i >> 2;
        int lane = idx4 & 31;
        int rest = idx4 >> 5;        // (j*3+kk)*4 + s
        int s    = rest & 3;
        int kkj  = rest >> 2;
        int kk   = kkj % 3;
        int j    = kkj / 3;
        int gid  = lane >> 2;
        int t4   = lane & 3;
        int m    = 16 * j + gid + 8 * (r & 1);
        u32 fr = 0;
#pragma unroll
        for (int e = 0; e < 2; e++) {
            int kappa = 16 * s + 2 * t4 + 8 * (r >> 1) + e;
            int c1    = chan_for_k(kappa);
            float wv  = w2[m * (NC1 * 3) + c1 * 3 + kk];
            __half hv = __float2half(wv);
            fr |= (u32)__half_as_ushort(hv) << (16 * e);
        }
        g_Af[i] = fr;
    }
}

// ---------------------------------------------------------------------------
// k_conv1: conv1 + threshold -> bit-packed spikes (TAU1=1 => stateless).
// Sliding-window register reuse over l (R13 version, unchanged).
// ---------------------------------------------------------------------------
__global__ __launch_bounds__(256) void k_conv1(
        const float* __restrict__ x,
        const float* __restrict__ w1,
        const float* __restrict__ b1,
        const float* __restrict__ pgain,
        const float* __restrict__ pth1) {
    __shared__ __align__(16) float s_x[CIN][34][TT];

    const int l0  = blockIdx.x * 32;
    const int b   = blockIdx.y;
    const int tid = threadIdx.x;

    for (int i = tid; i < CIN * 34 * TT; i += 256) {
        int c   = i / (34 * TT);
        int rem = i % (34 * TT);
        int lx  = rem / TT;
        int t   = rem % TT;
        int gl  = l0 - 1 + lx;
        float v = 0.0f;
        if (gl >= 0 && gl < LL)
            v = x[((size_t)(b * CIN + c) * LL + gl) * TT + t];
        s_x[c][lx][t] = v;
    }

    const int w    = tid >> 5;
    const int lane = tid & 31;
    const int half = w & 1;
    const int pair = w >> 1;
    const int c1   = half * 32 + lane;

    ull wrp[CIN][3];
#pragma unroll
    for (int c = 0; c < CIN; c++)
#pragma unroll
        for (int k = 0; k < 3; k++) {
            float wv = w1[c1 * (CIN * 3) + c * 3 + k];
            PACK_F32X2(wrp[c][k], wv, wv);
        }
    const float bias = b1[c1];
    const float gain = *pgain;
    const float th1  = *pth1;

    __syncthreads();

#pragma unroll 1
    for (int chunk = pair; chunk < 40; chunk += 4) {
        const int lc = chunk & 7;
        const int tg = chunk >> 3;
        const int t0 = tg * 4;

        ull acc[4][2];
#pragma unroll
        for (int l = 0; l < 4; l++) { acc[l][0] = 0ull; acc[l][1] = 0ull; }

#pragma unroll
        for (int c = 0; c < CIN; c++) {
            ulonglong2 row[6];
#pragma unroll
            for (int i = 0; i < 6; i++)
                row[i] = *(const ulonglong2*)&s_x[c][lc * 4 + i][t0];
#pragma unroll
            for (int l = 0; l < 4; l++)
#pragma unroll
                for (int k = 0; k < 3; k++) {
                    FMA_F32X2(acc[l][0], row[l + k].x, wrp[c][k], acc[l][0]);
                    FMA_F32X2(acc[l][1], row[l + k].y, wrp[c][k], acc[l][1]);
                }
        }

#pragma unroll
        for (int l = 0; l < 4; l++) {
            float a[4];
            UNPACK_F32X2(a[0], a[1], acc[l][0]);
            UNPACK_F32X2(a[2], a[3], acc[l][1]);
            int gl = l0 + lc * 4 + l;
#pragma unroll
            for (int jj = 0; jj < 4; jj++) {
                float i1 = (a[jj] + bias) * gain;
                u32 m = __ballot_sync(0xffffffffu, i1 >= th1);
                if (lane == 0)
                    g_s1[((size_t)(b * TT + t0 + jj) * LL + gl) * 2 + half] = m;
            }
        }
    }
}

// ---------------------------------------------------------------------------
// decode helper: spike word for one t -> fp16 fragment tile (64-l tile).
// Register-lean: 8 temps at a time, stores issued immediately.
// ---------------------------------------------------------------------------
__device__ __forceinline__ void decode_t(u32* Bt, u32 mc, int dh, int dn) {
    u32* r0 = Bt + ((2 * dh)     * NBR + dn) * 8;
    u32* r1 = Bt + ((2 * dh + 1) * NBR + dn) * 8;
    u32 o[8];
#pragma unroll
    for (int i = 0; i < 8; i++)
        o[i] = ((mc >> i) & 0x00010001u) * 0x3C00u;
    ((uint4*)r0)[0] = make_uint4(o[0], o[4], o[1], o[5]);
    ((uint4*)r0)[1] = make_uint4(o[2], o[6], o[3], o[7]);
#pragma unroll
    for (int i = 0; i < 8; i++)
        o[i] = ((mc >> (i + 8)) & 0x00010001u) * 0x3C00u;
    ((uint4*)r1)[0] = make_uint4(o[0], o[4], o[1], o[5]);
    ((uint4*)r1)[1] = make_uint4(o[2], o[6], o[3], o[7]);
}

// ---------------------------------------------------------------------------
// k_snn: conv2 via single-plane fp16 mma.sync; register-tightened so
// occupancy 2 holds WITHOUT spills (R16 was spilling ~30 regs under
// launch_bounds(256,2): A frags + decode temps bounced through local mem).
// Changes vs R16 (all bit-exact): acc 16->8 regs (nt processed in 2 halves,
// per-acc (s,kk) order unchanged), decode temps 16->8.
// smem: 2 x 2112 u32 B buffers = 16896 bytes.
// ---------------------------------------------------------------------------
#define SNN_SMEM (2 * 2112 * 4)

__global__ __launch_bounds__(256, 2) void k_snn(
        const float* __restrict__ b2,
        const float* __restrict__ pgain,
        const float* __restrict__ pth2) {
    extern __shared__ __align__(16) u32 Bs[];

    const int tid = threadIdx.x;
    const int b   = blockIdx.x >> 6;          // / NTILES
    const int l0  = (blockIdx.x & 63) * NLT;

    const int w    = tid >> 5;
    const int lane = tid & 31;
    const int j    = w & 3;       // m-tile (16 c2 rows)
    const int q    = (w >> 2) & 1;// n-half (32 l)
    const int gid  = lane >> 2;
    const int tid4 = lane & 3;

    // A fragments -> registers (L2-hot; identical for every CTA)
    uint4 afr[12];
#pragma unroll
    for (int s = 0; s < 4; s++)
#pragma unroll
        for (int kk = 0; kk < 3; kk++)
            afr[s * 3 + kk] =
                *(const uint4*)&g_Af[(((j * 3 + kk) * 4 + s) * 32 + lane) * 4];

    const float gain   = *pgain;
    const float th2    = *pth2;
    const float invtau = 1.0f / 0.9f;
    const float bia0   = b2[16 * j + gid];
    const float bia1   = b2[16 * j + gid + 8];

    // decode task assignment (132 tasks over 256 threads)
    const bool dact = tid < 132;
    int dh = 0, dn = 0;
    bool inrange = false;
    size_t gstep = 0, gaddr = 0;
    if (dact) {
        dh = (tid >= NBR) ? 1 : 0;
        dn = tid - NBR * dh;
        int gl  = l0 - 1 + dn;
        inrange = (gl >= 0 && gl < LL);
        if (inrange) {
            gaddr = ((size_t)(b * TT) * LL + gl) * 2 + dh;
            gstep = (size_t)LL * 2;
        }
    }

    float v2[16], cnt[16];
#pragma unroll
    for (int i = 0; i < 16; i++) { v2[i] = 0.0f; cnt[i] = 0.0f; }

    // ---- prologue: decode t=0 into buf 0; prefetch t=1 mask ----
    u32 mN = 0;
    if (dact) {
        u32 m0 = inrange ? g_s1[gaddr] : 0u;
        decode_t(Bs, m0, dh, dn);
        if (inrange) mN = g_s1[gaddr + gstep];
    }
    __syncthreads();

#pragma unroll 1
    for (int t = 0; t < TT; t++) {
        const int p = t & 1;
        u32* Bp = Bs + p * 2112;

        float acc[8];   // 2 nt x 4, reused across the two halves

        // ======== half 0: nt = 0,1 ========
#pragma unroll
        for (int i = 0; i < 8; i++) acc[i] = 0.0f;
#pragma unroll
        for (int s = 0; s < 4; s++) {
#pragma unroll
            for (int kk = 0; kk < 3; kk++) {
                uint4 af = afr[s * 3 + kk];
#pragma unroll
                for (int n2 = 0; n2 < 2; n2++) {
                    int boff = (s * NBR + q * 32 + n2 * 8 + gid + kk) * 8 + tid4 * 2;
                    uint2 bb = *(const uint2*)&Bp[boff];
                    MMA16816F((acc + n2 * 4), af, bb);
                }
            }
        }

        // ---- decode(t+1) into buf p^1 — overlaps tensor drain ----
        if (dact && t + 1 < TT) {
            decode_t(Bs + (p ^ 1) * 2112, mN, dh, dn);
            if (inrange && t + 2 < TT)
                mN = g_s1[gaddr + (size_t)(t + 2) * gstep];
        }

        // LIF half 0
#pragma unroll
        for (int n2 = 0; n2 < 2; n2++)
#pragma unroll
            for (int r = 0; r < 4; r++) {
                float bia = (r >> 1) ? bia1 : bia0;
                int idx = n2 * 4 + r;
                float i2 = (acc[n2 * 4 + r] + bia) * gain;
                v2[idx] += (i2 - v2[idx]) * invtau;
                if (v2[idx] >= th2) { cnt[idx] += 1.0f; v2[idx] = 0.0f; }
            }

        // ======== half 1: nt = 2,3 ========
#pragma unroll
        for (int i = 0; i < 8; i++) acc[i] = 0.0f;
#pragma unroll
        for (int s = 0; s < 4; s++) {
#pragma unroll
            for (int kk = 0; kk < 3; kk++) {
                uint4 af = afr[s * 3 + kk];
#pragma unroll
                for (int n2 = 0; n2 < 2; n2++) {
                    int boff = (s * NBR + q * 32 + (n2 + 2) * 8 + gid + kk) * 8 + tid4 * 2;
                    uint2 bb = *(const uint2*)&Bp[boff];
                    MMA16816F((acc + n2 * 4), af, bb);
                }
            }
        }

        // LIF half 1
#pragma unroll
        for (int n2 = 0; n2 < 2; n2++)
#pragma unroll
            for (int r = 0; r < 4; r++) {
                float bia = (r >> 1) ? bia1 : bia0;
                int idx = (n2 + 2) * 4 + r;
                float i2 = (acc[n2 * 4 + r] + bia) * gain;
                v2[idx] += (i2 - v2[idx]) * invtau;
                if (v2[idx] >= th2) { cnt[idx] += 1.0f; v2[idx] = 0.0f; }
            }

        __syncthreads();   // publish buf p^1; protect buf p for next decode
    }

    // ---- pool: sum counts per c2 ----
    float t0 = 0.0f, t1 = 0.0f;
#pragma unroll
    for (int nt = 0; nt < 4; nt++)
#pragma unroll
        for (int r = 0; r < 4; r++) {
            if (r >> 1) t1 += cnt[nt * 4 + r];
            else        t0 += cnt[nt * 4 + r];
        }
    t0 += __shfl_xor_sync(0xffffffffu, t0, 1);
    t0 += __shfl_xor_sync(0xffffffffu, t0, 2);
    t1 += __shfl_xor_sync(0xffffffffu, t1, 1);
    t1 += __shfl_xor_sync(0xffffffffu, t1, 2);
    if (tid4 == 0) {
        atomicAdd(&g_pool[b * NC2 + 16 * j + gid],     t0);   // integer-valued
        atomicAdd(&g_pool[b * NC2 + 16 * j + gid + 8], t1);
    }
}

// ---------------------------------------------------------------------------
// k_fc: pooled = counts / (T*L); logits = pooled @ fc_w.T + fc_b
// ---------------------------------------------------------------------------
__global__ void k_fc(const float* __restrict__ fw,
                     const float* __restrict__ fb,
                     float* __restrict__ out) {
    int tid = threadIdx.x;
    int b = tid >> 2;
    int n = tid & 3;
    const float sc = 1.0f / (float)(TT * LL);
    float s = fb[n];
#pragma unroll
    for (int c = 0; c < NC2; c++)
        s += (g_pool[b * NC2 + c] * sc) * fw[n * NC2 + c];
    out[b * NCLS + n] = s;
}

// ---------------------------------------------------------------------------
extern "C" void kernel_launch(void* const* d_in, const int* in_sizes, int n_in,
                              void* d_out, int out_size) {
    const float* x    = (const float*)d_in[0];
    const float* w1   = (const float*)d_in[1];
    const float* b1   = (const float*)d_in[2];
    const float* w2   = (const float*)d_in[3];
    const float* b2   = (const float*)d_in[4];
    const float* gain = (const float*)d_in[5];
    const float* th1  = (const float*)d_in[6];
    const float* th2  = (const float*)d_in[7];
    const float* fw   = (const float*)d_in[8];
    const float* fb   = (const float*)d_in[9];
    float* out = (float*)d_out;

    cudaFuncSetAttribute(k_snn, cudaFuncAttributeMaxDynamicSharedMemorySize,
                         SNN_SMEM);

    k_pre<<<24, 256>>>(w2);

    dim3 g1(LL / 32, BB);
    k_conv1<<<g1, 256>>>(x, w1, b1, gain, th1);

    k_snn<<<BB * NTILES, 256, SNN_SMEM>>>(b2, gain, th2);

    k_fc<<<1, 256>>>(fw, fb, out);
}